// round 6
// baseline (speedup 1.0000x reference)
#include <cuda_runtime.h>
#include <math.h>

#define H   64
#define G   192
#define NK  20
#define MM  512

// ---------------- scratch (no allocations allowed) ----------------
__device__ float g_hfin[10240 * H];     // final encoder hidden [10240,64]
__device__ float g_ssrc[10240];
__device__ float g_sdst[10240];
__device__ float g_h2[MM * NK * H];     // post-GAT/fc, layout [m][K][H]
__device__ float g_z[MM * NK * H];      // tanh(al_in)
__device__ float g_r[MM * NK * H];      // ALSTM GRU outputs, all steps

__device__ __forceinline__ float sigm(float x) {
    return __fdividef(1.f, 1.f + __expf(-x));
}

// ================= fused 2-layer GRU (persistent over T) =================
template <int DIN, int RPT>
__device__ __forceinline__ void gru_gemm(
    const float* __restrict__ xsrc, const float* __restrict__ hs,
    const float* __restrict__ Wti, const float* __restrict__ Wth,
    const float* __restrict__ bi, const float* __restrict__ bh,
    float* __restrict__ gs, float* __restrict__ xns, int tx, int ty)
{
    float acc[RPT][6], xn[RPT][2];
#pragma unroll
    for (int jj = 0; jj < 6; jj++) {
        float b = bh[tx + 32 * jj] + (jj < 4 ? bi[tx + 32 * jj] : 0.f);
#pragma unroll
        for (int rr = 0; rr < RPT; rr++) acc[rr][jj] = b;
    }
#pragma unroll
    for (int rr = 0; rr < RPT; rr++) {
        xn[rr][0] = bi[tx + 128];
        xn[rr][1] = bi[tx + 160];
    }
    // x-part
#pragma unroll 2
    for (int k = 0; k < DIN; k++) {
        float w0 = Wti[k * G + tx],       w1 = Wti[k * G + tx + 32];
        float w2 = Wti[k * G + tx + 64],  w3 = Wti[k * G + tx + 96];
        float w4 = Wti[k * G + tx + 128], w5 = Wti[k * G + tx + 160];
#pragma unroll
        for (int rr = 0; rr < RPT; rr++) {
            float xv = xsrc[(ty * RPT + rr) * DIN + k];
            acc[rr][0] += xv * w0; acc[rr][1] += xv * w1;
            acc[rr][2] += xv * w2; acc[rr][3] += xv * w3;
            xn[rr][0]  += xv * w4; xn[rr][1]  += xv * w5;
        }
    }
    // h-part
#pragma unroll 2
    for (int k = 0; k < H; k++) {
        float w0 = Wth[k * G + tx],       w1 = Wth[k * G + tx + 32];
        float w2 = Wth[k * G + tx + 64],  w3 = Wth[k * G + tx + 96];
        float w4 = Wth[k * G + tx + 128], w5 = Wth[k * G + tx + 160];
#pragma unroll
        for (int rr = 0; rr < RPT; rr++) {
            float hv = hs[(ty * RPT + rr) * H + k];
            acc[rr][0] += hv * w0; acc[rr][1] += hv * w1; acc[rr][2] += hv * w2;
            acc[rr][3] += hv * w3; acc[rr][4] += hv * w4; acc[rr][5] += hv * w5;
        }
    }
#pragma unroll
    for (int jj = 0; jj < 6; jj++)
#pragma unroll
        for (int rr = 0; rr < RPT; rr++)
            gs[(ty * RPT + rr) * G + tx + 32 * jj] = acc[rr][jj];
#pragma unroll
    for (int rr = 0; rr < RPT; rr++) {
        xns[(ty * RPT + rr) * H + tx]      = xn[rr][0];
        xns[(ty * RPT + rr) * H + tx + 32] = xn[rr][1];
    }
}

template <int RP, int NT>
__device__ __forceinline__ void gru_update(float* __restrict__ hs,
                                           const float* __restrict__ gs,
                                           const float* __restrict__ xns, int tid)
{
    for (int u = tid; u < RP * H; u += NT) {
        int row = u >> 6, d = u & 63;
        float r = sigm(gs[row * G + d]);
        float z = sigm(gs[row * G + 64 + d]);
        float n = tanhf(xns[u] + r * gs[row * G + 128 + d]);
        hs[u] = (1.f - z) * n + z * hs[u];
    }
}

template <int DIN, int RPT, int WARPS, bool STORE_ALL>
__global__ __launch_bounds__(32 * WARPS, 1) void gru2_kernel(
    const float* __restrict__ x, int Tn, int Nn,
    const float* __restrict__ Wih0, const float* __restrict__ Whh0,
    const float* __restrict__ bih0, const float* __restrict__ bhh0,
    const float* __restrict__ Wih1, const float* __restrict__ Whh1,
    const float* __restrict__ bih1, const float* __restrict__ bhh1,
    float* __restrict__ out)
{
    constexpr int RP = RPT * WARPS;
    constexpr int NT = 32 * WARPS;
    extern __shared__ float sm[];
    float* Wti0 = sm;                    // [DIN][192] transposed
    float* Wth0 = Wti0 + DIN * G;        // [64][192]
    float* Wti1 = Wth0 + H * G;
    float* Wth1 = Wti1 + H * G;
    float* bi0  = Wth1 + H * G;
    float* bh0 = bi0 + G; float* bi1 = bh0 + G; float* bh1 = bi1 + G;
    float* h0s = bh1 + G;                // RP*64
    float* h1s = h0s + RP * H;
    float* xs  = h1s + RP * H;           // RP*DIN
    float* gs  = xs + RP * DIN;          // RP*192
    float* xns = gs + RP * G;            // RP*64

    int tx = threadIdx.x, ty = threadIdx.y, tid = ty * 32 + tx;
    for (int idx = tid; idx < DIN * G; idx += NT) {
        int j = idx / DIN, k = idx % DIN;
        Wti0[k * G + j] = Wih0[idx];
    }
    for (int idx = tid; idx < H * G; idx += NT) {
        int j = idx >> 6, k = idx & 63;
        Wth0[k * G + j] = Whh0[idx];
        Wti1[k * G + j] = Wih1[idx];
        Wth1[k * G + j] = Whh1[idx];
    }
    for (int idx = tid; idx < G; idx += NT) {
        bi0[idx] = bih0[idx]; bh0[idx] = bhh0[idx];
        bi1[idx] = bih1[idx]; bh1[idx] = bhh1[idx];
    }
    for (int idx = tid; idx < RP * H; idx += NT) { h0s[idx] = 0.f; h1s[idx] = 0.f; }
    __syncthreads();

    int row0 = blockIdx.x * RP;
    int nrows = Nn - row0; if (nrows > RP) nrows = RP;

    for (int t = 0; t < Tn; t++) {
        for (int idx = tid; idx < RP * DIN; idx += NT) {
            int r2 = idx / DIN, d2 = idx % DIN;
            xs[idx] = (r2 < nrows)
                ? x[((size_t)(row0 + r2) * Tn + t) * DIN + d2] : 0.f;
        }
        __syncthreads();
        gru_gemm<DIN, RPT>(xs, h0s, Wti0, Wth0, bi0, bh0, gs, xns, tx, ty);
        __syncthreads();
        gru_update<RP, NT>(h0s, gs, xns, tid);
        __syncthreads();
        gru_gemm<H, RPT>(h0s, h1s, Wti1, Wth1, bi1, bh1, gs, xns, tx, ty);
        __syncthreads();
        gru_update<RP, NT>(h1s, gs, xns, tid);
        __syncthreads();
        if (STORE_ALL) {
            for (int idx = tid; idx < nrows * H; idx += NT) {
                int r2 = idx >> 6, d2 = idx & 63;
                out[((size_t)(row0 + r2) * Tn + t) * H + d2] = h1s[idx];
            }
            __syncthreads();
        }
    }
    if (!STORE_ALL) {
        for (int idx = tid; idx < nrows * H; idx += NT)
            out[(size_t)row0 * H + idx] = h1s[idx];
    }
}

// ========== trans projection + attention score scalars (per encoder row) ====
__global__ __launch_bounds__(64) void trans_score_kernel(
    const float* __restrict__ hfin,
    const float* __restrict__ W, const float* __restrict__ b,
    const float* __restrict__ a,
    float* __restrict__ ssrc, float* __restrict__ sdst)
{
    __shared__ float Wt[H * H], bs[H], as[2 * H], hrow[H], red[H], red2[H];
    int d = threadIdx.x;  // 64 threads
    for (int idx = d; idx < H * H; idx += 64)
        Wt[(idx & 63) * H + (idx >> 6)] = W[idx];
    bs[d] = b[d]; as[d] = a[d]; as[H + d] = a[H + d];
    __syncthreads();
    for (int rr = 0; rr < 16; rr++) {
        int n = blockIdx.x * 16 + rr;
        hrow[d] = hfin[(size_t)n * H + d];
        __syncthreads();
        float xp = bs[d];
#pragma unroll 8
        for (int k = 0; k < H; k++) xp += hrow[k] * Wt[k * H + d];
        red[d] = xp * as[d];       // -> s_dst (a[:H])
        red2[d] = xp * as[H + d];  // -> s_src (a[H:])
        __syncthreads();
        for (int s2 = 32; s2 > 0; s2 >>= 1) {
            if (d < s2) { red[d] += red[d + s2]; red2[d] += red2[d + s2]; }
            __syncthreads();
        }
        if (d == 0) { sdst[n] = red[0]; ssrc[n] = red2[0]; }
        __syncthreads();
    }
}

// ====== GAT: softmax(leakyrelu(s_i + s_j)) @ h + h, then fc, write [m][K][H]
__global__ __launch_bounds__(256, 1) void gat_kernel(
    const float* __restrict__ hfin, const float* __restrict__ ssrc,
    const float* __restrict__ sdst, const float* __restrict__ fcW,
    const float* __restrict__ fcb, float* __restrict__ h2)
{
    extern __shared__ float s[];
    float* hs   = s;                 // [512][64]
    float* fWt  = hs + MM * H;       // [64][64] transposed
    float* sd   = fWt + H * H;       // 512
    float* wj   = sd + MM;           // 512
    float* rowv = wj + MM;           // 64
    float* part = rowv + H;          // 4*64
    float* red  = part + 4 * H;      // 8

    int t = threadIdx.x;
    int k = blockIdx.y;
    int base = k * MM;
    const float4* src4 = (const float4*)(hfin + (size_t)base * H);
    float4* hs4 = (float4*)hs;
    for (int idx = t; idx < MM * (H / 4); idx += 256) hs4[idx] = src4[idx];
    for (int idx = t; idx < H * H; idx += 256)
        fWt[(idx & 63) * H + (idx >> 6)] = fcW[idx];
    for (int idx = t; idx < MM; idx += 256) sd[idx] = sdst[base + idx];
    __syncthreads();

    int lane = t & 31, wid = t >> 5;
    for (int r = 0; r < 64; r++) {
        int i = blockIdx.x * 64 + r;
        float si = ssrc[base + i];
        float v0 = si + sd[t];       v0 = v0 > 0.f ? v0 : 0.01f * v0;
        float v1 = si + sd[t + 256]; v1 = v1 > 0.f ? v1 : 0.01f * v1;
        float mx = fmaxf(v0, v1);
#pragma unroll
        for (int o = 16; o > 0; o >>= 1) mx = fmaxf(mx, __shfl_xor_sync(~0u, mx, o));
        if (lane == 0) red[wid] = mx;
        __syncthreads();
        mx = red[0];
#pragma unroll
        for (int q = 1; q < 8; q++) mx = fmaxf(mx, red[q]);
        float e0 = __expf(v0 - mx), e1 = __expf(v1 - mx);
        wj[t] = e0; wj[t + 256] = e1;
        float sum = e0 + e1;
#pragma unroll
        for (int o = 16; o > 0; o >>= 1) sum += __shfl_xor_sync(~0u, sum, o);
        __syncthreads();                 // everyone done reading red (max)
        if (lane == 0) red[wid] = sum;
        __syncthreads();
        sum = 0.f;
#pragma unroll
        for (int q = 0; q < 8; q++) sum += red[q];
        float inv = __fdividef(1.f, sum);

        int d = t & 63, q = t >> 6;
        float acc = 0.f;
        const float* hp = hs + q * 128 * H + d;
        const float* wp = wj + q * 128;
#pragma unroll 8
        for (int j = 0; j < 128; j++) acc += wp[j] * hp[j * H];
        part[q * H + d] = acc;
        __syncthreads();
        if (t < H) {
            rowv[t] = (part[t] + part[H + t] + part[2 * H + t] + part[3 * H + t]) * inv
                      + hs[i * H + t];
        }
        __syncthreads();
        if (t < H) {
            float acc2 = fcb[t];
#pragma unroll 8
            for (int dd = 0; dd < H; dd++) acc2 += rowv[dd] * fWt[dd * H + t];
            h2[((size_t)i * NK + k) * H + t] = acc2;
        }
        __syncthreads();
    }
}

// ============== rowwise linear + tanh (for al_in) ==============
__global__ __launch_bounds__(64) void lin_tanh_kernel(
    const float* __restrict__ in, const float* __restrict__ W,
    const float* __restrict__ b, float* __restrict__ out)
{
    __shared__ float Wt[H * H], bs[H], hrow[H];
    int d = threadIdx.x;
    for (int idx = d; idx < H * H; idx += 64)
        Wt[(idx & 63) * H + (idx >> 6)] = W[idx];
    bs[d] = b[d];
    __syncthreads();
    for (int rr = 0; rr < 16; rr++) {
        size_t n = (size_t)blockIdx.x * 16 + rr;
        hrow[d] = in[n * H + d];
        __syncthreads();
        float acc = bs[d];
#pragma unroll 8
        for (int k = 0; k < H; k++) acc += hrow[k] * Wt[k * H + d];
        out[n * H + d] = tanhf(acc);
        __syncthreads();
    }
}

// ============== ALSTM attention + outputs ==============
__global__ __launch_bounds__(64) void final_kernel(
    const float* __restrict__ r, const float* __restrict__ h2,
    const float* __restrict__ att1W, const float* __restrict__ att1b,
    const float* __restrict__ att2W,
    const float* __restrict__ aloutW, const float* __restrict__ aloutb,
    const float* __restrict__ fcoW, const float* __restrict__ fcob,
    float* __restrict__ out)
{
    __shared__ float a1t[32 * H];   // transposed [k][j]
    __shared__ float e[NK], rrow[H], red2[2];
    int t = threadIdx.x;
    int n = blockIdx.x;
    for (int idx = t; idx < 32 * H; idx += 64)
        a1t[(idx & 63) * 32 + (idx >> 6)] = att1W[idx];
    __syncthreads();

    for (int tt = 0; tt < NK; tt++) {
        rrow[t] = r[((size_t)n * NK + tt) * H + t];
        __syncthreads();
        if (t < 32) {
            float acc = att1b[t];
#pragma unroll 8
            for (int k = 0; k < H; k++) acc += rrow[k] * a1t[k * 32 + t];
            float v = tanhf(acc) * att2W[t];
#pragma unroll
            for (int o = 16; o > 0; o >>= 1) v += __shfl_xor_sync(~0u, v, o);
            if (t == 0) e[tt] = v;
        }
        __syncthreads();
    }
    // softmax over K (each thread recomputes from smem; broadcast reads)
    float mx = e[0];
#pragma unroll
    for (int tt = 1; tt < NK; tt++) mx = fmaxf(mx, e[tt]);
    float sum = 0.f;
#pragma unroll
    for (int tt = 0; tt < NK; tt++) sum += __expf(e[tt] - mx);
    float inv = __fdividef(1.f, sum);

    float oa = 0.f;
#pragma unroll
    for (int tt = 0; tt < NK; tt++)
        oa += __expf(e[tt] - mx) * inv * r[((size_t)n * NK + tt) * H + t];

    float rl = r[((size_t)n * NK + (NK - 1)) * H + t];
    float p = rl * aloutW[t] + oa * aloutW[H + t];
#pragma unroll
    for (int o = 16; o > 0; o >>= 1) p += __shfl_xor_sync(~0u, p, o);
    if ((t & 31) == 0) red2[t >> 5] = p;
    __syncthreads();
    if (t == 0) out[n] = red2[0] + red2[1] + aloutb[0];
    __syncthreads();

    float hv = h2[((size_t)n * NK + (NK - 1)) * H + t];
    hv = hv > 0.f ? hv : 0.01f * hv;
    float pp = hv * fcoW[t];
#pragma unroll
    for (int o = 16; o > 0; o >>= 1) pp += __shfl_xor_sync(~0u, pp, o);
    if ((t & 31) == 0) red2[t >> 5] = pp;
    __syncthreads();
    if (t == 0) out[MM + n] = red2[0] + red2[1] + fcob[0];
}

// ============================ launcher ============================
extern "C" void kernel_launch(void* const* d_in, const int* in_sizes, int n_in,
                              void* d_out, int out_size) {
    const float* x        = (const float*)d_in[0];
    const float* rWih0    = (const float*)d_in[1];
    const float* rWhh0    = (const float*)d_in[2];
    const float* rbih0    = (const float*)d_in[3];
    const float* rbhh0    = (const float*)d_in[4];
    const float* rWih1    = (const float*)d_in[5];
    const float* rWhh1    = (const float*)d_in[6];
    const float* rbih1    = (const float*)d_in[7];
    const float* rbhh1    = (const float*)d_in[8];
    const float* trans_W  = (const float*)d_in[9];
    const float* trans_b  = (const float*)d_in[10];
    const float* a_vec    = (const float*)d_in[11];
    const float* fc_W     = (const float*)d_in[12];
    const float* fc_b     = (const float*)d_in[13];
    const float* fco_W    = (const float*)d_in[14];
    const float* fco_b    = (const float*)d_in[15];
    const float* al_in_W  = (const float*)d_in[16];
    const float* al_in_b  = (const float*)d_in[17];
    const float* aWih0    = (const float*)d_in[18];
    const float* aWhh0    = (const float*)d_in[19];
    const float* abih0    = (const float*)d_in[20];
    const float* abhh0    = (const float*)d_in[21];
    const float* aWih1    = (const float*)d_in[22];
    const float* aWhh1    = (const float*)d_in[23];
    const float* abih1    = (const float*)d_in[24];
    const float* abhh1    = (const float*)d_in[25];
    const float* att1_W   = (const float*)d_in[26];
    const float* att1_b   = (const float*)d_in[27];
    const float* att2_W   = (const float*)d_in[28];
    const float* alout_W  = (const float*)d_in[29];
    const float* alout_b  = (const float*)d_in[30];

    float *hfin, *ssrc, *sdst, *h2, *z, *r;
    cudaGetSymbolAddress((void**)&hfin, g_hfin);
    cudaGetSymbolAddress((void**)&ssrc, g_ssrc);
    cudaGetSymbolAddress((void**)&sdst, g_sdst);
    cudaGetSymbolAddress((void**)&h2,   g_h2);
    cudaGetSymbolAddress((void**)&z,    g_z);
    cudaGetSymbolAddress((void**)&r,    g_r);

    // dynamic smem sizes
    const size_t smem1 = (size_t)((6 + 3 * H) * G + 4 * G
                          + 2 * 40 * H + 40 * 6 + 40 * G + 40 * H) * 4;   // 217,536 B
    const size_t smem3 = (size_t)(4 * H * G + 4 * G
                          + 2 * 4 * H + 4 * H + 4 * G + 4 * H) * 4;       // 206,848 B
    const size_t smemg = (size_t)(MM * H + H * H + MM + MM + H + 4 * H + 8) * 4; // 152,864 B

    cudaFuncSetAttribute(gru2_kernel<6, 5, 8, false>,
                         cudaFuncAttributeMaxDynamicSharedMemorySize, (int)smem1);
    cudaFuncSetAttribute(gru2_kernel<64, 1, 4, true>,
                         cudaFuncAttributeMaxDynamicSharedMemorySize, (int)smem3);
    cudaFuncSetAttribute(gat_kernel,
                         cudaFuncAttributeMaxDynamicSharedMemorySize, (int)smemg);

    // 1. encoder 2-layer GRU: 10240 rows, T=60, D=6 -> hfin
    gru2_kernel<6, 5, 8, false><<<256, dim3(32, 8), smem1>>>(
        x, 60, 10240, rWih0, rWhh0, rbih0, rbhh0, rWih1, rWhh1, rbih1, rbhh1, hfin);

    // 2. trans projection + per-row attention scalars
    trans_score_kernel<<<640, 64>>>(hfin, trans_W, trans_b, a_vec, ssrc, sdst);

    // 3. GAT softmax-attention + residual + fc -> h2 [m][K][H]
    gat_kernel<<<dim3(8, NK), 256, smemg>>>(hfin, ssrc, sdst, fc_W, fc_b, h2);

    // 4. z = tanh(h2 @ al_in_W.T + b)
    lin_tanh_kernel<<<640, 64>>>(h2, al_in_W, al_in_b, z);

    // 5. ALSTM 2-layer GRU over K=20, batch 512 -> r (all steps)
    gru2_kernel<64, 1, 4, true><<<128, dim3(32, 4), smem3>>>(
        z, NK, MM, aWih0, aWhh0, abih0, abhh0, aWih1, aWhh1, abih1, abhh1, r);

    // 6. attention pooling + output heads
    final_kernel<<<MM, 64>>>(r, h2, att1_W, att1_b, att2_W,
                             alout_W, alout_b, fco_W, fco_b, (float*)d_out);
}

// round 7
// speedup vs baseline: 1.3819x; 1.3819x over previous
#include <cuda_runtime.h>
#include <math.h>

#define H   64
#define G   192
#define NK  20
#define MM  512

typedef unsigned long long u64t;

// ---------------- scratch (no allocations allowed) ----------------
__device__ float g_hfin[10240 * H];     // final encoder hidden [10240,64]
__device__ float g_ssrc[10240];
__device__ float g_sdst[10240];
__device__ float g_h2[MM * NK * H];     // post-GAT/fc, layout [m][K][H]
__device__ float g_z[MM * NK * H];      // tanh(al_in)
__device__ float g_r[MM * NK * H];      // ALSTM GRU outputs, all steps

__device__ __forceinline__ float sigm(float x) {
    return __fdividef(1.f, 1.f + __expf(-x));
}
// saturating fast tanh: 1 - 2/(e^{2x}+1); exact at +-inf, ~1e-6 abs err
__device__ __forceinline__ float tanh_(float x) {
    float e = __expf(2.f * x);
    return 1.f - __fdividef(2.f, e + 1.f);
}

__device__ __forceinline__ u64t pk2(float x, float y) {
    u64t r; asm("mov.b64 %0, {%1,%2};" : "=l"(r) : "f"(x), "f"(y)); return r;
}
__device__ __forceinline__ u64t ffma2(u64t a, u64t b, u64t c) {
    u64t d; asm("fma.rn.f32x2 %0, %1, %2, %3;" : "=l"(d) : "l"(a), "l"(b), "l"(c));
    return d;
}
__device__ __forceinline__ void unpk2(u64t v, float& x, float& y) {
    asm("mov.b64 {%0,%1}, %2;" : "=f"(x), "=f"(y) : "l"(v));
}

// ---- accumulate src[row][0..DK) @ Wt[k][192] into 3 col-pair acc sets ----
// thread tx owns column pairs (2tx, 2tx+1), (+64), (+128).
template <int DK, int RPT>
__device__ __forceinline__ void gemm_acc(
    const float* __restrict__ src,   // warp-local rows, scalar [row][DK]
    const float* __restrict__ Wt,    // transposed [k][192]
    u64t* __restrict__ A, u64t* __restrict__ B, u64t* __restrict__ C,
    int tx)
{
#pragma unroll 2
    for (int k = 0; k < DK; k += 2) {
        const u64t* w0r = (const u64t*)(Wt + k * G);
        const u64t* w1r = (const u64t*)(Wt + (k + 1) * G);
        u64t wa0 = w0r[tx], wb0 = w0r[tx + 32], wc0 = w0r[tx + 64];
        u64t wa1 = w1r[tx], wb1 = w1r[tx + 32], wc1 = w1r[tx + 64];
#pragma unroll
        for (int rr = 0; rr < RPT; rr++) {
            float2 hv = *(const float2*)(src + rr * DK + k);
            u64t d0 = pk2(hv.x, hv.x);
            u64t d1 = pk2(hv.y, hv.y);
            A[rr] = ffma2(d0, wa0, A[rr]);
            B[rr] = ffma2(d0, wb0, B[rr]);
            C[rr] = ffma2(d0, wc0, C[rr]);
            A[rr] = ffma2(d1, wa1, A[rr]);
            B[rr] = ffma2(d1, wb1, B[rr]);
            C[rr] = ffma2(d1, wc1, C[rr]);
        }
    }
}

// ---- in-register GRU pointwise update; h stored scalar [row][64] ----
template <int RPT>
__device__ __forceinline__ void gru_point(
    const u64t* __restrict__ A, const u64t* __restrict__ B,
    const u64t* __restrict__ C, const u64t* __restrict__ XN,
    float* __restrict__ hw, int tx, float2* __restrict__ nv)
{
    const int j0 = 2 * tx;
#pragma unroll
    for (int rr = 0; rr < RPT; rr++) {
        float ra, rb, za, zb, ha, hb, xa, xb;
        unpk2(A[rr], ra, rb); unpk2(B[rr], za, zb);
        unpk2(C[rr], ha, hb); unpk2(XN[rr], xa, xb);
        float r0 = sigm(ra), r1 = sigm(rb);
        float z0 = sigm(za), z1 = sigm(zb);
        float n0 = tanh_(xa + r0 * ha), n1 = tanh_(xb + r1 * hb);
        float2 hold = *(const float2*)(hw + rr * H + j0);
        nv[rr].x = (1.f - z0) * n0 + z0 * hold.x;
        nv[rr].y = (1.f - z1) * n1 + z1 * hold.y;
    }
    __syncwarp();
#pragma unroll
    for (int rr = 0; rr < RPT; rr++)
        *(float2*)(hw + rr * H + j0) = nv[rr];
    __syncwarp();
}

// ================= fused 2-layer GRU, warp-private rows, no block barriers ==
template <int DIN, int RPT, int WARPS, bool STORE_ALL>
__global__ __launch_bounds__(32 * WARPS, 1) void gru2_kernel(
    const float* __restrict__ x, int Tn, int Nn,
    const float* __restrict__ Wih0, const float* __restrict__ Whh0,
    const float* __restrict__ bih0, const float* __restrict__ bhh0,
    const float* __restrict__ Wih1, const float* __restrict__ Whh1,
    const float* __restrict__ bih1, const float* __restrict__ bhh1,
    float* __restrict__ out)
{
    constexpr int RP = RPT * WARPS;
    constexpr int NT = 32 * WARPS;
    constexpr int XSPAD = (RPT * DIN + 1) & ~1;
    extern __shared__ float sm[];
    float* Wti0 = sm;                    // [DIN][192] transposed
    float* Wth0 = Wti0 + DIN * G;        // [64][192]
    float* Wti1 = Wth0 + H * G;
    float* Wth1 = Wti1 + H * G;
    float* bi0  = Wth1 + H * G;
    float* bh0 = bi0 + G; float* bi1 = bh0 + G; float* bh1 = bi1 + G;
    float* h0s = bh1 + G;                // RP*64 scalar
    float* h1s = h0s + RP * H;
    float* xsS = h1s + RP * H;           // WARPS*XSPAD

    int tx = threadIdx.x, ty = threadIdx.y, tid = ty * 32 + tx;
    for (int idx = tid; idx < DIN * G; idx += NT) {
        int j = idx / DIN, k = idx - j * DIN;
        Wti0[k * G + j] = Wih0[idx];
    }
    for (int idx = tid; idx < H * G; idx += NT) {
        int j = idx >> 6, k = idx & 63;
        Wth0[k * G + j] = Whh0[idx];
        Wti1[k * G + j] = Wih1[idx];
        Wth1[k * G + j] = Whh1[idx];
    }
    for (int idx = tid; idx < G; idx += NT) {
        bi0[idx] = bih0[idx]; bh0[idx] = bhh0[idx];
        bi1[idx] = bih1[idx]; bh1[idx] = bhh1[idx];
    }
    for (int idx = tid; idx < RP * H; idx += NT) { h0s[idx] = 0.f; h1s[idx] = 0.f; }
    __syncthreads();

    const int rowbase = blockIdx.x * RP + ty * RPT;
    float* h0w = h0s + ty * RPT * H;
    float* h1w = h1s + ty * RPT * H;
    float* xw  = xsS + ty * XSPAD;
    const int j0 = 2 * tx;

    for (int t = 0; t < Tn; t++) {
        // warp-local x load
        for (int i = tx; i < RPT * DIN; i += 32) {
            int rr = i / DIN, dd = i - rr * DIN;
            int grow = rowbase + rr;
            xw[i] = (grow < Nn) ? x[((size_t)grow * Tn + t) * DIN + dd] : 0.f;
        }
        __syncwarp();

        u64t A[RPT], B[RPT], C[RPT], XN[RPT];
        float2 nv[RPT];
        // ---- layer 0 ----
        {
            u64t bA = pk2(bi0[j0] + bh0[j0], bi0[j0 + 1] + bh0[j0 + 1]);
            u64t bB = pk2(bi0[j0 + 64] + bh0[j0 + 64], bi0[j0 + 65] + bh0[j0 + 65]);
            u64t bC = pk2(bh0[j0 + 128], bh0[j0 + 129]);
            u64t bN = pk2(bi0[j0 + 128], bi0[j0 + 129]);
#pragma unroll
            for (int rr = 0; rr < RPT; rr++) { A[rr]=bA; B[rr]=bB; C[rr]=bC; XN[rr]=bN; }
        }
        gemm_acc<DIN, RPT>(xw,  Wti0, A, B, XN, tx);   // x-part (n x-part -> XN)
        gemm_acc<H,   RPT>(h0w, Wth0, A, B, C,  tx);   // h-part
        gru_point<RPT>(A, B, C, XN, h0w, tx, nv);
        // ---- layer 1 ----
        {
            u64t bA = pk2(bi1[j0] + bh1[j0], bi1[j0 + 1] + bh1[j0 + 1]);
            u64t bB = pk2(bi1[j0 + 64] + bh1[j0 + 64], bi1[j0 + 65] + bh1[j0 + 65]);
            u64t bC = pk2(bh1[j0 + 128], bh1[j0 + 129]);
            u64t bN = pk2(bi1[j0 + 128], bi1[j0 + 129]);
#pragma unroll
            for (int rr = 0; rr < RPT; rr++) { A[rr]=bA; B[rr]=bB; C[rr]=bC; XN[rr]=bN; }
        }
        gemm_acc<H, RPT>(h0w, Wti1, A, B, XN, tx);
        gemm_acc<H, RPT>(h1w, Wth1, A, B, C,  tx);
        gru_point<RPT>(A, B, C, XN, h1w, tx, nv);

        if (STORE_ALL) {
#pragma unroll
            for (int rr = 0; rr < RPT; rr++) {
                int grow = rowbase + rr;
                if (grow < Nn)
                    *(float2*)(out + ((size_t)grow * Tn + t) * H + j0) = nv[rr];
            }
        }
    }
    if (!STORE_ALL) {
#pragma unroll
        for (int rr = 0; rr < RPT; rr++) {
            int grow = rowbase + rr;
            if (grow < Nn)
                *(float2*)(out + (size_t)grow * H + j0) =
                    *(const float2*)(h1w + rr * H + j0);
        }
    }
}

// ========== trans projection + attention score scalars (per encoder row) ====
__global__ __launch_bounds__(64) void trans_score_kernel(
    const float* __restrict__ hfin,
    const float* __restrict__ W, const float* __restrict__ b,
    const float* __restrict__ a,
    float* __restrict__ ssrc, float* __restrict__ sdst)
{
    __shared__ float Wt[H * H], bs[H], as[2 * H], hrow[H], red[H], red2[H];
    int d = threadIdx.x;  // 64 threads
    for (int idx = d; idx < H * H; idx += 64)
        Wt[(idx & 63) * H + (idx >> 6)] = W[idx];
    bs[d] = b[d]; as[d] = a[d]; as[H + d] = a[H + d];
    __syncthreads();
    for (int rr = 0; rr < 4; rr++) {
        int n = blockIdx.x * 4 + rr;
        hrow[d] = hfin[(size_t)n * H + d];
        __syncthreads();
        float xp = bs[d];
#pragma unroll 8
        for (int k = 0; k < H; k++) xp += hrow[k] * Wt[k * H + d];
        red[d] = xp * as[d];       // -> s_dst (a[:H])
        red2[d] = xp * as[H + d];  // -> s_src (a[H:])
        __syncthreads();
        for (int s2 = 32; s2 > 0; s2 >>= 1) {
            if (d < s2) { red[d] += red[d + s2]; red2[d] += red2[d + s2]; }
            __syncthreads();
        }
        if (d == 0) { sdst[n] = red[0]; ssrc[n] = red2[0]; }
        __syncthreads();
    }
}

// ====== GAT: softmax(leakyrelu(s_i + s_j)) @ h + h, then fc, write [m][K][H]
__global__ __launch_bounds__(256, 1) void gat_kernel(
    const float* __restrict__ hfin, const float* __restrict__ ssrc,
    const float* __restrict__ sdst, const float* __restrict__ fcW,
    const float* __restrict__ fcb, float* __restrict__ h2)
{
    extern __shared__ float s[];
    float* hs   = s;                 // [512][64]
    float* fWt  = hs + MM * H;       // [64][64] transposed
    float* sd   = fWt + H * H;       // 512
    float* wj   = sd + MM;           // 512
    float* rowv = wj + MM;           // 64
    float* part = rowv + H;          // 4*64
    float* red  = part + 4 * H;      // 8

    int t = threadIdx.x;
    int k = blockIdx.y;
    int base = k * MM;
    const float4* src4 = (const float4*)(hfin + (size_t)base * H);
    float4* hs4 = (float4*)hs;
    for (int idx = t; idx < MM * (H / 4); idx += 256) hs4[idx] = src4[idx];
    for (int idx = t; idx < H * H; idx += 256)
        fWt[(idx & 63) * H + (idx >> 6)] = fcW[idx];
    for (int idx = t; idx < MM; idx += 256) sd[idx] = sdst[base + idx];
    __syncthreads();

    int lane = t & 31, wid = t >> 5;
    for (int r = 0; r < 64; r++) {
        int i = blockIdx.x * 64 + r;
        float si = ssrc[base + i];
        float v0 = si + sd[t];       v0 = v0 > 0.f ? v0 : 0.01f * v0;
        float v1 = si + sd[t + 256]; v1 = v1 > 0.f ? v1 : 0.01f * v1;
        float mx = fmaxf(v0, v1);
#pragma unroll
        for (int o = 16; o > 0; o >>= 1) mx = fmaxf(mx, __shfl_xor_sync(~0u, mx, o));
        if (lane == 0) red[wid] = mx;
        __syncthreads();
        mx = red[0];
#pragma unroll
        for (int q = 1; q < 8; q++) mx = fmaxf(mx, red[q]);
        float e0 = __expf(v0 - mx), e1 = __expf(v1 - mx);
        wj[t] = e0; wj[t + 256] = e1;
        float sum = e0 + e1;
#pragma unroll
        for (int o = 16; o > 0; o >>= 1) sum += __shfl_xor_sync(~0u, sum, o);
        __syncthreads();                 // everyone done reading red (max)
        if (lane == 0) red[wid] = sum;
        __syncthreads();
        sum = 0.f;
#pragma unroll
        for (int q = 0; q < 8; q++) sum += red[q];
        float inv = __fdividef(1.f, sum);

        int d = t & 63, q = t >> 6;
        float acc = 0.f;
        const float* hp = hs + q * 128 * H + d;
        const float* wp = wj + q * 128;
#pragma unroll 8
        for (int j = 0; j < 128; j++) acc += wp[j] * hp[j * H];
        part[q * H + d] = acc;
        __syncthreads();
        if (t < H) {
            rowv[t] = (part[t] + part[H + t] + part[2 * H + t] + part[3 * H + t]) * inv
                      + hs[i * H + t];
        }
        __syncthreads();
        if (t < H) {
            float acc2 = fcb[t];
#pragma unroll 8
            for (int dd = 0; dd < H; dd++) acc2 += rowv[dd] * fWt[dd * H + t];
            h2[((size_t)i * NK + k) * H + t] = acc2;
        }
        __syncthreads();
    }
}

// ============== rowwise linear + tanh (for al_in) ==============
__global__ __launch_bounds__(64) void lin_tanh_kernel(
    const float* __restrict__ in, const float* __restrict__ W,
    const float* __restrict__ b, float* __restrict__ out)
{
    __shared__ float Wt[H * H], bs[H], hrow[H];
    int d = threadIdx.x;
    for (int idx = d; idx < H * H; idx += 64)
        Wt[(idx & 63) * H + (idx >> 6)] = W[idx];
    bs[d] = b[d];
    __syncthreads();
    for (int rr = 0; rr < 4; rr++) {
        size_t n = (size_t)blockIdx.x * 4 + rr;
        hrow[d] = in[n * H + d];
        __syncthreads();
        float acc = bs[d];
#pragma unroll 8
        for (int k = 0; k < H; k++) acc += hrow[k] * Wt[k * H + d];
        out[n * H + d] = tanhf(acc);
        __syncthreads();
    }
}

// ============== ALSTM attention + outputs ==============
__global__ __launch_bounds__(64) void final_kernel(
    const float* __restrict__ r, const float* __restrict__ h2,
    const float* __restrict__ att1W, const float* __restrict__ att1b,
    const float* __restrict__ att2W,
    const float* __restrict__ aloutW, const float* __restrict__ aloutb,
    const float* __restrict__ fcoW, const float* __restrict__ fcob,
    float* __restrict__ out)
{
    __shared__ float a1t[32 * H];   // transposed [k][j]
    __shared__ float e[NK], rrow[H], red2[2];
    int t = threadIdx.x;
    int n = blockIdx.x;
    for (int idx = t; idx < 32 * H; idx += 64)
        a1t[(idx & 63) * 32 + (idx >> 6)] = att1W[idx];
    __syncthreads();

    for (int tt = 0; tt < NK; tt++) {
        rrow[t] = r[((size_t)n * NK + tt) * H + t];
        __syncthreads();
        if (t < 32) {
            float acc = att1b[t];
#pragma unroll 8
            for (int k = 0; k < H; k++) acc += rrow[k] * a1t[k * 32 + t];
            float v = tanhf(acc) * att2W[t];
#pragma unroll
            for (int o = 16; o > 0; o >>= 1) v += __shfl_xor_sync(~0u, v, o);
            if (t == 0) e[tt] = v;
        }
        __syncthreads();
    }
    float mx = e[0];
#pragma unroll
    for (int tt = 1; tt < NK; tt++) mx = fmaxf(mx, e[tt]);
    float sum = 0.f;
#pragma unroll
    for (int tt = 0; tt < NK; tt++) sum += __expf(e[tt] - mx);
    float inv = __fdividef(1.f, sum);

    float oa = 0.f;
#pragma unroll
    for (int tt = 0; tt < NK; tt++)
        oa += __expf(e[tt] - mx) * inv * r[((size_t)n * NK + tt) * H + t];

    float rl = r[((size_t)n * NK + (NK - 1)) * H + t];
    float p = rl * aloutW[t] + oa * aloutW[H + t];
#pragma unroll
    for (int o = 16; o > 0; o >>= 1) p += __shfl_xor_sync(~0u, p, o);
    if ((t & 31) == 0) red2[t >> 5] = p;
    __syncthreads();
    if (t == 0) out[n] = red2[0] + red2[1] + aloutb[0];
    __syncthreads();

    float hv = h2[((size_t)n * NK + (NK - 1)) * H + t];
    hv = hv > 0.f ? hv : 0.01f * hv;
    float pp = hv * fcoW[t];
#pragma unroll
    for (int o = 16; o > 0; o >>= 1) pp += __shfl_xor_sync(~0u, pp, o);
    if ((t & 31) == 0) red2[t >> 5] = pp;
    __syncthreads();
    if (t == 0) out[MM + n] = red2[0] + red2[1] + fcob[0];
}

// ============================ launcher ============================
extern "C" void kernel_launch(void* const* d_in, const int* in_sizes, int n_in,
                              void* d_out, int out_size) {
    const float* x        = (const float*)d_in[0];
    const float* rWih0    = (const float*)d_in[1];
    const float* rWhh0    = (const float*)d_in[2];
    const float* rbih0    = (const float*)d_in[3];
    const float* rbhh0    = (const float*)d_in[4];
    const float* rWih1    = (const float*)d_in[5];
    const float* rWhh1    = (const float*)d_in[6];
    const float* rbih1    = (const float*)d_in[7];
    const float* rbhh1    = (const float*)d_in[8];
    const float* trans_W  = (const float*)d_in[9];
    const float* trans_b  = (const float*)d_in[10];
    const float* a_vec    = (const float*)d_in[11];
    const float* fc_W     = (const float*)d_in[12];
    const float* fc_b     = (const float*)d_in[13];
    const float* fco_W    = (const float*)d_in[14];
    const float* fco_b    = (const float*)d_in[15];
    const float* al_in_W  = (const float*)d_in[16];
    const float* al_in_b  = (const float*)d_in[17];
    const float* aWih0    = (const float*)d_in[18];
    const float* aWhh0    = (const float*)d_in[19];
    const float* abih0    = (const float*)d_in[20];
    const float* abhh0    = (const float*)d_in[21];
    const float* aWih1    = (const float*)d_in[22];
    const float* aWhh1    = (const float*)d_in[23];
    const float* abih1    = (const float*)d_in[24];
    const float* abhh1    = (const float*)d_in[25];
    const float* att1_W   = (const float*)d_in[26];
    const float* att1_b   = (const float*)d_in[27];
    const float* att2_W   = (const float*)d_in[28];
    const float* alout_W  = (const float*)d_in[29];
    const float* alout_b  = (const float*)d_in[30];

    float *hfin, *ssrc, *sdst, *h2, *z, *r;
    cudaGetSymbolAddress((void**)&hfin, g_hfin);
    cudaGetSymbolAddress((void**)&ssrc, g_ssrc);
    cudaGetSymbolAddress((void**)&sdst, g_sdst);
    cudaGetSymbolAddress((void**)&h2,   g_h2);
    cudaGetSymbolAddress((void**)&z,    g_z);
    cudaGetSymbolAddress((void**)&r,    g_r);

    // encoder: DIN=6, RPT=5, WARPS=7 -> RP=35, 293 CTAs (2 balanced waves)
    const size_t smem1 = (size_t)(6 * G + 3 * H * G + 4 * G
                          + 2 * 35 * H + 7 * 30) * 4;                        // 173,952 B
    // alstm: DIN=64, RPT=1, WARPS=4 -> RP=4, 128 CTAs
    const size_t smem3 = (size_t)(4 * H * G + 4 * G + 2 * 4 * H + 4 * 64) * 4; // 202,752 B
    const size_t smemg = (size_t)(MM * H + H * H + MM + MM + H + 4 * H + 8) * 4;

    cudaFuncSetAttribute(gru2_kernel<6, 5, 7, false>,
                         cudaFuncAttributeMaxDynamicSharedMemorySize, (int)smem1);
    cudaFuncSetAttribute(gru2_kernel<64, 1, 4, true>,
                         cudaFuncAttributeMaxDynamicSharedMemorySize, (int)smem3);
    cudaFuncSetAttribute(gat_kernel,
                         cudaFuncAttributeMaxDynamicSharedMemorySize, (int)smemg);

    // 1. encoder 2-layer GRU: 10240 rows, T=60, D=6 -> hfin
    gru2_kernel<6, 5, 7, false><<<293, dim3(32, 7), smem1>>>(
        x, 60, 10240, rWih0, rWhh0, rbih0, rbhh0, rWih1, rWhh1, rbih1, rbhh1, hfin);

    // 2. trans projection + per-row attention scalars
    trans_score_kernel<<<2560, 64>>>(hfin, trans_W, trans_b, a_vec, ssrc, sdst);

    // 3. GAT softmax-attention + residual + fc -> h2 [m][K][H]
    gat_kernel<<<dim3(8, NK), 256, smemg>>>(hfin, ssrc, sdst, fc_W, fc_b, h2);

    // 4. z = tanh(h2 @ al_in_W.T + b)
    lin_tanh_kernel<<<2560, 64>>>(h2, al_in_W, al_in_b, z);

    // 5. ALSTM 2-layer GRU over K=20, batch 512 -> r (all steps)
    gru2_kernel<64, 1, 4, true><<<128, dim3(32, 4), smem3>>>(
        z, NK, MM, aWih0, aWhh0, abih0, abhh0, aWih1, aWhh1, abih1, abhh1, r);

    // 6. attention pooling + output heads
    final_kernel<<<MM, 64>>>(r, h2, att1_W, att1_b, att2_W,
                             alout_W, alout_b, fco_W, fco_b, (float*)d_out);
}

// round 12
// speedup vs baseline: 1.3865x; 1.0033x over previous
#include <cuda_runtime.h>
#include <math.h>

#define H   64
#define G   192
#define NK  20
#define MM  512

typedef unsigned long long u64t;

// ---------------- scratch (no allocations allowed) ----------------
__device__ float g_hfin[10240 * H];     // final encoder hidden [10240,64]
__device__ float g_ssrc[10240];
__device__ float g_sdst[10240];
__device__ float g_h2[MM * NK * H];     // post-GAT/fc, layout [m][K][H]
__device__ float g_z[MM * NK * H];      // tanh(al_in)
__device__ float g_r[MM * NK * H];      // ALSTM GRU outputs, all steps

__device__ __forceinline__ float sigm(float x) {
    return __fdividef(1.f, 1.f + __expf(-x));
}
// saturating fast tanh: 1 - 2/(e^{2x}+1); exact at +-inf, ~1e-6 abs err
__device__ __forceinline__ float tanh_(float x) {
    float e = __expf(2.f * x);
    return 1.f - __fdividef(2.f, e + 1.f);
}

__device__ __forceinline__ u64t pk2(float x, float y) {
    u64t r; asm("mov.b64 %0, {%1,%2};" : "=l"(r) : "f"(x), "f"(y)); return r;
}
__device__ __forceinline__ u64t ffma2(u64t a, u64t b, u64t c) {
    u64t d; asm("fma.rn.f32x2 %0, %1, %2, %3;" : "=l"(d) : "l"(a), "l"(b), "l"(c));
    return d;
}
__device__ __forceinline__ void unpk2(u64t v, float& x, float& y) {
    asm("mov.b64 {%0,%1}, %2;" : "=f"(x), "=f"(y) : "l"(v));
}

// ---- accumulate src[row][0..DK) @ Wt[k][192] into 3 col-pair acc sets ----
// thread tx owns column pairs (2tx, 2tx+1), (+64), (+128).
template <int DK, int RPT>
__device__ __forceinline__ void gemm_acc(
    const float* __restrict__ src,   // warp-local rows, scalar [row][DK]
    const float* __restrict__ Wt,    // transposed [k][192]
    u64t* __restrict__ A, u64t* __restrict__ B, u64t* __restrict__ C,
    int tx)
{
#pragma unroll 2
    for (int k = 0; k < DK; k += 2) {
        const u64t* w0r = (const u64t*)(Wt + k * G);
        const u64t* w1r = (const u64t*)(Wt + (k + 1) * G);
        u64t wa0 = w0r[tx], wb0 = w0r[tx + 32], wc0 = w0r[tx + 64];
        u64t wa1 = w1r[tx], wb1 = w1r[tx + 32], wc1 = w1r[tx + 64];
#pragma unroll
        for (int rr = 0; rr < RPT; rr++) {
            float2 hv = *(const float2*)(src + rr * DK + k);
            u64t d0 = pk2(hv.x, hv.x);
            u64t d1 = pk2(hv.y, hv.y);
            A[rr] = ffma2(d0, wa0, A[rr]);
            B[rr] = ffma2(d0, wb0, B[rr]);
            C[rr] = ffma2(d0, wc0, C[rr]);
            A[rr] = ffma2(d1, wa1, A[rr]);
            B[rr] = ffma2(d1, wb1, B[rr]);
            C[rr] = ffma2(d1, wc1, C[rr]);
        }
    }
}

// ---- in-register GRU pointwise update; h stored scalar [row][64] ----
template <int RPT>
__device__ __forceinline__ void gru_point(
    const u64t* __restrict__ A, const u64t* __restrict__ B,
    const u64t* __restrict__ C, const u64t* __restrict__ XN,
    float* __restrict__ hw, int tx, float2* __restrict__ nv)
{
    const int j0 = 2 * tx;
#pragma unroll
    for (int rr = 0; rr < RPT; rr++) {
        float ra, rb, za, zb, ha, hb, xa, xb;
        unpk2(A[rr], ra, rb); unpk2(B[rr], za, zb);
        unpk2(C[rr], ha, hb); unpk2(XN[rr], xa, xb);
        float r0 = sigm(ra), r1 = sigm(rb);
        float z0 = sigm(za), z1 = sigm(zb);
        float n0 = tanh_(xa + r0 * ha), n1 = tanh_(xb + r1 * hb);
        float2 hold = *(const float2*)(hw + rr * H + j0);
        nv[rr].x = (1.f - z0) * n0 + z0 * hold.x;
        nv[rr].y = (1.f - z1) * n1 + z1 * hold.y;
    }
    __syncwarp();
#pragma unroll
    for (int rr = 0; rr < RPT; rr++)
        *(float2*)(hw + rr * H + j0) = nv[rr];
    __syncwarp();
}

// ================= fused 2-layer GRU, warp-private rows, no block barriers ==
template <int DIN, int RPT, int WARPS, bool STORE_ALL>
__global__ __launch_bounds__(32 * WARPS, 1) void gru2_kernel(
    const float* __restrict__ x, int Tn, int Nn,
    const float* __restrict__ Wih0, const float* __restrict__ Whh0,
    const float* __restrict__ bih0, const float* __restrict__ bhh0,
    const float* __restrict__ Wih1, const float* __restrict__ Whh1,
    const float* __restrict__ bih1, const float* __restrict__ bhh1,
    float* __restrict__ out)
{
    constexpr int RP = RPT * WARPS;
    constexpr int NT = 32 * WARPS;
    constexpr int XSPAD = (RPT * DIN + 1) & ~1;
    extern __shared__ float sm[];
    float* Wti0 = sm;                    // [DIN][192] transposed
    float* Wth0 = Wti0 + DIN * G;        // [64][192]
    float* Wti1 = Wth0 + H * G;
    float* Wth1 = Wti1 + H * G;
    float* bi0  = Wth1 + H * G;
    float* bh0 = bi0 + G; float* bi1 = bh0 + G; float* bh1 = bi1 + G;
    float* h0s = bh1 + G;                // RP*64 scalar
    float* h1s = h0s + RP * H;
    float* xsS = h1s + RP * H;           // WARPS*XSPAD

    int tx = threadIdx.x, ty = threadIdx.y, tid = ty * 32 + tx;
    for (int idx = tid; idx < DIN * G; idx += NT) {
        int j = idx / DIN, k = idx - j * DIN;
        Wti0[k * G + j] = Wih0[idx];
    }
    for (int idx = tid; idx < H * G; idx += NT) {
        int j = idx >> 6, k = idx & 63;
        Wth0[k * G + j] = Whh0[idx];
        Wti1[k * G + j] = Wih1[idx];
        Wth1[k * G + j] = Whh1[idx];
    }
    for (int idx = tid; idx < G; idx += NT) {
        bi0[idx] = bih0[idx]; bh0[idx] = bhh0[idx];
        bi1[idx] = bih1[idx]; bh1[idx] = bhh1[idx];
    }
    for (int idx = tid; idx < RP * H; idx += NT) { h0s[idx] = 0.f; h1s[idx] = 0.f; }
    __syncthreads();

    const int rowbase = blockIdx.x * RP + ty * RPT;
    float* h0w = h0s + ty * RPT * H;
    float* h1w = h1s + ty * RPT * H;
    float* xw  = xsS + ty * XSPAD;
    const int j0 = 2 * tx;

    for (int t = 0; t < Tn; t++) {
        // warp-local x load
        for (int i = tx; i < RPT * DIN; i += 32) {
            int rr = i / DIN, dd = i - rr * DIN;
            int grow = rowbase + rr;
            xw[i] = (grow < Nn) ? x[((size_t)grow * Tn + t) * DIN + dd] : 0.f;
        }
        __syncwarp();

        u64t A[RPT], B[RPT], C[RPT], XN[RPT];
        float2 nv[RPT];
        // ---- layer 0 ----
        {
            u64t bA = pk2(bi0[j0] + bh0[j0], bi0[j0 + 1] + bh0[j0 + 1]);
            u64t bB = pk2(bi0[j0 + 64] + bh0[j0 + 64], bi0[j0 + 65] + bh0[j0 + 65]);
            u64t bC = pk2(bh0[j0 + 128], bh0[j0 + 129]);
            u64t bN = pk2(bi0[j0 + 128], bi0[j0 + 129]);
#pragma unroll
            for (int rr = 0; rr < RPT; rr++) { A[rr]=bA; B[rr]=bB; C[rr]=bC; XN[rr]=bN; }
        }
        gemm_acc<DIN, RPT>(xw,  Wti0, A, B, XN, tx);   // x-part (n x-part -> XN)
        gemm_acc<H,   RPT>(h0w, Wth0, A, B, C,  tx);   // h-part
        gru_point<RPT>(A, B, C, XN, h0w, tx, nv);
        // ---- layer 1 ----
        {
            u64t bA = pk2(bi1[j0] + bh1[j0], bi1[j0 + 1] + bh1[j0 + 1]);
            u64t bB = pk2(bi1[j0 + 64] + bh1[j0 + 64], bi1[j0 + 65] + bh1[j0 + 65]);
            u64t bC = pk2(bh1[j0 + 128], bh1[j0 + 129]);
            u64t bN = pk2(bi1[j0 + 128], bi1[j0 + 129]);
#pragma unroll
            for (int rr = 0; rr < RPT; rr++) { A[rr]=bA; B[rr]=bB; C[rr]=bC; XN[rr]=bN; }
        }
        gemm_acc<H, RPT>(h0w, Wti1, A, B, XN, tx);
        gemm_acc<H, RPT>(h1w, Wth1, A, B, C,  tx);
        gru_point<RPT>(A, B, C, XN, h1w, tx, nv);

        if (STORE_ALL) {
#pragma unroll
            for (int rr = 0; rr < RPT; rr++) {
                int grow = rowbase + rr;
                if (grow < Nn)
                    *(float2*)(out + ((size_t)grow * Tn + t) * H + j0) = nv[rr];
            }
        }
    }
    if (!STORE_ALL) {
#pragma unroll
        for (int rr = 0; rr < RPT; rr++) {
            int grow = rowbase + rr;
            if (grow < Nn)
                *(float2*)(out + (size_t)grow * H + j0) =
                    *(const float2*)(h1w + rr * H + j0);
        }
    }
}

// ========== trans projection + attention score scalars (per encoder row) ====
__global__ __launch_bounds__(64) void trans_score_kernel(
    const float* __restrict__ hfin,
    const float* __restrict__ W, const float* __restrict__ b,
    const float* __restrict__ a,
    float* __restrict__ ssrc, float* __restrict__ sdst)
{
    __shared__ float Wt[H * H], bs[H], as[2 * H], hrow[H], red[H], red2[H];
    int d = threadIdx.x;  // 64 threads
    for (int idx = d; idx < H * H; idx += 64)
        Wt[(idx & 63) * H + (idx >> 6)] = W[idx];
    bs[d] = b[d]; as[d] = a[d]; as[H + d] = a[H + d];
    __syncthreads();
    for (int rr = 0; rr < 4; rr++) {
        int n = blockIdx.x * 4 + rr;
        hrow[d] = hfin[(size_t)n * H + d];
        __syncthreads();
        float xp = bs[d];
#pragma unroll 8
        for (int k = 0; k < H; k++) xp += hrow[k] * Wt[k * H + d];
        red[d] = xp * as[d];       // -> s_dst (a[:H])
        red2[d] = xp * as[H + d];  // -> s_src (a[H:])
        __syncthreads();
        for (int s2 = 32; s2 > 0; s2 >>= 1) {
            if (d < s2) { red[d] += red[d + s2]; red2[d] += red2[d + s2]; }
            __syncthreads();
        }
        if (d == 0) { sdst[n] = red[0]; ssrc[n] = red2[0]; }
        __syncthreads();
    }
}

// ====== GAT: softmax(leakyrelu(s_i + s_j)) @ h + h, then fc, write [m][K][H]
__global__ __launch_bounds__(256, 1) void gat_kernel(
    const float* __restrict__ hfin, const float* __restrict__ ssrc,
    const float* __restrict__ sdst, const float* __restrict__ fcW,
    const float* __restrict__ fcb, float* __restrict__ h2)
{
    extern __shared__ float s[];
    float* hs   = s;                 // [512][64]
    float* fWt  = hs + MM * H;       // [64][64] transposed
    float* sd   = fWt + H * H;       // 512
    float* wj   = sd + MM;           // 512
    float* rowv = wj + MM;           // 64
    float* part = rowv + H;          // 4*64
    float* red  = part + 4 * H;      // 8

    int t = threadIdx.x;
    int k = blockIdx.y;
    int base = k * MM;
    const float4* src4 = (const float4*)(hfin + (size_t)base * H);
    float4* hs4 = (float4*)hs;
    for (int idx = t; idx < MM * (H / 4); idx += 256) hs4[idx] = src4[idx];
    for (int idx = t; idx < H * H; idx += 256)
        fWt[(idx & 63) * H + (idx >> 6)] = fcW[idx];
    for (int idx = t; idx < MM; idx += 256) sd[idx] = sdst[base + idx];
    __syncthreads();

    int lane = t & 31, wid = t >> 5;
    for (int r = 0; r < 64; r++) {
        int i = blockIdx.x * 64 + r;
        float si = ssrc[base + i];
        float v0 = si + sd[t];       v0 = v0 > 0.f ? v0 : 0.01f * v0;
        float v1 = si + sd[t + 256]; v1 = v1 > 0.f ? v1 : 0.01f * v1;
        float mx = fmaxf(v0, v1);
#pragma unroll
        for (int o = 16; o > 0; o >>= 1) mx = fmaxf(mx, __shfl_xor_sync(~0u, mx, o));
        if (lane == 0) red[wid] = mx;
        __syncthreads();
        mx = red[0];
#pragma unroll
        for (int q = 1; q < 8; q++) mx = fmaxf(mx, red[q]);
        float e0 = __expf(v0 - mx), e1 = __expf(v1 - mx);
        wj[t] = e0; wj[t + 256] = e1;
        float sum = e0 + e1;
#pragma unroll
        for (int o = 16; o > 0; o >>= 1) sum += __shfl_xor_sync(~0u, sum, o);
        __syncthreads();                 // everyone done reading red (max)
        if (lane == 0) red[wid] = sum;
        __syncthreads();
        sum = 0.f;
#pragma unroll
        for (int q = 0; q < 8; q++) sum += red[q];
        float inv = __fdividef(1.f, sum);

        int d = t & 63, q = t >> 6;
        float acc = 0.f;
        const float* hp = hs + q * 128 * H + d;
        const float* wp = wj + q * 128;
#pragma unroll 8
        for (int j = 0; j < 128; j++) acc += wp[j] * hp[j * H];
        part[q * H + d] = acc;
        __syncthreads();
        if (t < H) {
            rowv[t] = (part[t] + part[H + t] + part[2 * H + t] + part[3 * H + t]) * inv
                      + hs[i * H + t];
        }
        __syncthreads();
        if (t < H) {
            float acc2 = fcb[t];
#pragma unroll 8
            for (int dd = 0; dd < H; dd++) acc2 += rowv[dd] * fWt[dd * H + t];
            h2[((size_t)i * NK + k) * H + t] = acc2;
        }
        __syncthreads();
    }
}

// ============== rowwise linear + tanh (for al_in) ==============
__global__ __launch_bounds__(64) void lin_tanh_kernel(
    const float* __restrict__ in, const float* __restrict__ W,
    const float* __restrict__ b, float* __restrict__ out)
{
    __shared__ float Wt[H * H], bs[H], hrow[H];
    int d = threadIdx.x;
    for (int idx = d; idx < H * H; idx += 64)
        Wt[(idx & 63) * H + (idx >> 6)] = W[idx];
    bs[d] = b[d];
    __syncthreads();
    for (int rr = 0; rr < 4; rr++) {
        size_t n = (size_t)blockIdx.x * 4 + rr;
        hrow[d] = in[n * H + d];
        __syncthreads();
        float acc = bs[d];
#pragma unroll 8
        for (int k = 0; k < H; k++) acc += hrow[k] * Wt[k * H + d];
        out[n * H + d] = tanhf(acc);
        __syncthreads();
    }
}

// ============== ALSTM attention + outputs ==============
__global__ __launch_bounds__(64) void final_kernel(
    const float* __restrict__ r, const float* __restrict__ h2,
    const float* __restrict__ att1W, const float* __restrict__ att1b,
    const float* __restrict__ att2W,
    const float* __restrict__ aloutW, const float* __restrict__ aloutb,
    const float* __restrict__ fcoW, const float* __restrict__ fcob,
    float* __restrict__ out)
{
    __shared__ float a1t[32 * H];   // transposed [k][j]
    __shared__ float e[NK], rrow[H], red2[2];
    int t = threadIdx.x;
    int n = blockIdx.x;
    for (int idx = t; idx < 32 * H; idx += 64)
        a1t[(idx & 63) * 32 + (idx >> 6)] = att1W[idx];
    __syncthreads();

    for (int tt = 0; tt < NK; tt++) {
        rrow[t] = r[((size_t)n * NK + tt) * H + t];
        __syncthreads();
        if (t < 32) {
            float acc = att1b[t];
#pragma unroll 8
            for (int k = 0; k < H; k++) acc += rrow[k] * a1t[k * 32 + t];
            float v = tanhf(acc) * att2W[t];
#pragma unroll
            for (int o = 16; o > 0; o >>= 1) v += __shfl_xor_sync(~0u, v, o);
            if (t == 0) e[tt] = v;
        }
        __syncthreads();
    }
    float mx = e[0];
#pragma unroll
    for (int tt = 1; tt < NK; tt++) mx = fmaxf(mx, e[tt]);
    float sum = 0.f;
#pragma unroll
    for (int tt = 0; tt < NK; tt++) sum += __expf(e[tt] - mx);
    float inv = __fdividef(1.f, sum);

    float oa = 0.f;
#pragma unroll
    for (int tt = 0; tt < NK; tt++)
        oa += __expf(e[tt] - mx) * inv * r[((size_t)n * NK + tt) * H + t];

    float rl = r[((size_t)n * NK + (NK - 1)) * H + t];
    float p = rl * aloutW[t] + oa * aloutW[H + t];
#pragma unroll
    for (int o = 16; o > 0; o >>= 1) p += __shfl_xor_sync(~0u, p, o);
    if ((t & 31) == 0) red2[t >> 5] = p;
    __syncthreads();
    if (t == 0) out[n] = red2[0] + red2[1] + aloutb[0];
    __syncthreads();

    float hv = h2[((size_t)n * NK + (NK - 1)) * H + t];
    hv = hv > 0.f ? hv : 0.01f * hv;
    float pp = hv * fcoW[t];
#pragma unroll
    for (int o = 16; o > 0; o >>= 1) pp += __shfl_xor_sync(~0u, pp, o);
    if ((t & 31) == 0) red2[t >> 5] = pp;
    __syncthreads();
    if (t == 0) out[MM + n] = red2[0] + red2[1] + fcob[0];
}

// ============================ launcher ============================
extern "C" void kernel_launch(void* const* d_in, const int* in_sizes, int n_in,
                              void* d_out, int out_size) {
    const float* x        = (const float*)d_in[0];
    const float* rWih0    = (const float*)d_in[1];
    const float* rWhh0    = (const float*)d_in[2];
    const float* rbih0    = (const float*)d_in[3];
    const float* rbhh0    = (const float*)d_in[4];
    const float* rWih1    = (const float*)d_in[5];
    const float* rWhh1    = (const float*)d_in[6];
    const float* rbih1    = (const float*)d_in[7];
    const float* rbhh1    = (const float*)d_in[8];
    const float* trans_W  = (const float*)d_in[9];
    const float* trans_b  = (const float*)d_in[10];
    const float* a_vec    = (const float*)d_in[11];
    const float* fc_W     = (const float*)d_in[12];
    const float* fc_b     = (const float*)d_in[13];
    const float* fco_W    = (const float*)d_in[14];
    const float* fco_b    = (const float*)d_in[15];
    const float* al_in_W  = (const float*)d_in[16];
    const float* al_in_b  = (const float*)d_in[17];
    const float* aWih0    = (const float*)d_in[18];
    const float* aWhh0    = (const float*)d_in[19];
    const float* abih0    = (const float*)d_in[20];
    const float* abhh0    = (const float*)d_in[21];
    const float* aWih1    = (const float*)d_in[22];
    const float* aWhh1    = (const float*)d_in[23];
    const float* abih1    = (const float*)d_in[24];
    const float* abhh1    = (const float*)d_in[25];
    const float* att1_W   = (const float*)d_in[26];
    const float* att1_b   = (const float*)d_in[27];
    const float* att2_W   = (const float*)d_in[28];
    const float* alout_W  = (const float*)d_in[29];
    const float* alout_b  = (const float*)d_in[30];

    float *hfin, *ssrc, *sdst, *h2, *z, *r;
    cudaGetSymbolAddress((void**)&hfin, g_hfin);
    cudaGetSymbolAddress((void**)&ssrc, g_ssrc);
    cudaGetSymbolAddress((void**)&sdst, g_sdst);
    cudaGetSymbolAddress((void**)&h2,   g_h2);
    cudaGetSymbolAddress((void**)&z,    g_z);
    cudaGetSymbolAddress((void**)&r,    g_r);

    // encoder: DIN=6, RPT=5, WARPS=7 -> RP=35, 293 CTAs (2 balanced waves)
    const size_t smem1 = (size_t)(6 * G + 3 * H * G + 4 * G
                          + 2 * 35 * H + 7 * 30) * 4;                        // 173,952 B
    // alstm: DIN=64, RPT=1, WARPS=4 -> RP=4, 128 CTAs
    const size_t smem3 = (size_t)(4 * H * G + 4 * G + 2 * 4 * H + 4 * 64) * 4; // 202,752 B
    const size_t smemg = (size_t)(MM * H + H * H + MM + MM + H + 4 * H + 8) * 4;

    cudaFuncSetAttribute(gru2_kernel<6, 5, 7, false>,
                         cudaFuncAttributeMaxDynamicSharedMemorySize, (int)smem1);
    cudaFuncSetAttribute(gru2_kernel<64, 1, 4, true>,
                         cudaFuncAttributeMaxDynamicSharedMemorySize, (int)smem3);
    cudaFuncSetAttribute(gat_kernel,
                         cudaFuncAttributeMaxDynamicSharedMemorySize, (int)smemg);

    // 1. encoder 2-layer GRU: 10240 rows, T=60, D=6 -> hfin
    gru2_kernel<6, 5, 7, false><<<293, dim3(32, 7), smem1>>>(
        x, 60, 10240, rWih0, rWhh0, rbih0, rbhh0, rWih1, rWhh1, rbih1, rbhh1, hfin);

    // 2. trans projection + per-row attention scalars
    trans_score_kernel<<<2560, 64>>>(hfin, trans_W, trans_b, a_vec, ssrc, sdst);

    // 3. GAT softmax-attention + residual + fc -> h2 [m][K][H]
    gat_kernel<<<dim3(8, NK), 256, smemg>>>(hfin, ssrc, sdst, fc_W, fc_b, h2);

    // 4. z = tanh(h2 @ al_in_W.T + b)
    lin_tanh_kernel<<<2560, 64>>>(h2, al_in_W, al_in_b, z);

    // 5. ALSTM 2-layer GRU over K=20, batch 512 -> r (all steps)
    gru2_kernel<64, 1, 4, true><<<128, dim3(32, 4), smem3>>>(
        z, NK, MM, aWih0, aWhh0, abih0, abhh0, aWih1, aWhh1, abih1, abhh1, r);

    // 6. attention pooling + output heads
    final_kernel<<<MM, 64>>>(r, h2, att1_W, att1_b, att2_W,
                             alout_W, alout_b, fco_W, fco_b, (float*)d_out);
}

// round 14
// speedup vs baseline: 2.0791x; 1.4995x over previous
#include <cuda_runtime.h>
#include <cuda_bf16.h>
#include <math.h>

#define H   64
#define G   192
#define NK  20
#define MM  512

typedef unsigned int u32;
typedef unsigned long long u64t;

__device__ float g_hfin[10240 * H];
__device__ float g_ssrc[10240];
__device__ float g_sdst[10240];
__device__ float g_h2[MM * NK * H];
__device__ float g_z[MM * NK * H];
__device__ float g_r[MM * NK * H];

__device__ __forceinline__ float sigm(float x) {
    return __fdividef(1.f, 1.f + __expf(-x));
}
__device__ __forceinline__ float tanh_(float x) {
    float e = __expf(2.f * x);
    return 1.f - __fdividef(2.f, e + 1.f);
}
__device__ __forceinline__ u32 pkbf(float x, float y) {
    __nv_bfloat162 v = __floats2bfloat162_rn(x, y); return *(u32*)&v;
}
__device__ __forceinline__ float2 upbf(u32 u) {
    __nv_bfloat162 v = *(__nv_bfloat162*)&u;
    return make_float2(__bfloat162float(v.x), __bfloat162float(v.y));
}
__device__ __forceinline__ void mma16816(float* c, const u32* a, u32 b0, u32 b1) {
    asm volatile("mma.sync.aligned.m16n8k16.row.col.f32.bf16.bf16.f32 "
        "{%0,%1,%2,%3},{%4,%5,%6,%7},{%8,%9},{%0,%1,%2,%3};"
        : "+f"(c[0]), "+f"(c[1]), "+f"(c[2]), "+f"(c[3])
        : "r"(a[0]), "r"(a[1]), "r"(a[2]), "r"(a[3]), "r"(b0), "r"(b1));
}
__device__ __forceinline__ void ldm4(u32* r, u32 sa) {
    asm volatile("ldmatrix.sync.aligned.m8n8.x4.shared.b16 {%0,%1,%2,%3},[%4];"
        : "=r"(r[0]), "=r"(r[1]), "=r"(r[2]), "=r"(r[3]) : "r"(sa));
}
#define MMA3(C, AH, AL, WHV, WLV) do {                               \
    u32 _b0 = (u32)(WHV), _b1 = (u32)((WHV) >> 32);                  \
    u32 _c0 = (u32)(WLV), _c1 = (u32)((WLV) >> 32);                  \
    mma16816(C, AH, _b0, _b1);                                       \
    mma16816(C, AL, _b0, _b1);                                       \
    mma16816(C, AH, _c0, _c1); } while (0)

__device__ __forceinline__ float dot6(const float* xr, const float* Wi0, int j, float b) {
    float a = b;
#pragma unroll
    for (int k = 0; k < 6; k++) a += xr[k] * Wi0[j * 6 + k];
    return a;
}

// smem byte offsets
#define OFF_WL   73728
#define OFF_H0H  147456
#define OFF_H0L  165888
#define OFF_H1H  184320
#define OFF_H1L  202752
#define OFF_WI0  221184
#define OFF_BI0  225792
#define OFF_BH0  226560
#define OFF_BS1  227328
#define OFF_BI1N 227840
#define OFF_BH1N 228096
#define OFF_XST  228352
#define SMEM_TC  231424
#define IX(m, gate, c, kt) ((m) * 3072 + ((((gate) * 8 + (c)) * 4 + (kt)) * 32) + lane)

// ====== tensor-core fused 2-layer GRU encoder: 80 CTAs x 8 warps x 16 rows ==
__global__ __launch_bounds__(256, 1) void gru_tc_kernel(
    const float* __restrict__ x,
    const float* __restrict__ Wih0, const float* __restrict__ bih0,
    const float* __restrict__ Whh0, const float* __restrict__ bhh0,
    const float* __restrict__ Wih1, const float* __restrict__ bih1,
    const float* __restrict__ Whh1, const float* __restrict__ bhh1,
    float* __restrict__ hfin)
{
    extern __shared__ __align__(16) unsigned char smb[];
    u64t* WH = (u64t*)smb;                       // [3][3072] hi-plane B frags
    u64t* WL = (u64t*)(smb + OFF_WL);
    u32* h0h = (u32*)(smb + OFF_H0H);            // h planes: [128][36] u32
    u32* h0l = (u32*)(smb + OFF_H0L);
    u32* h1h = (u32*)(smb + OFF_H1H);
    u32* h1l = (u32*)(smb + OFF_H1L);
    float* Wi0  = (float*)(smb + OFF_WI0);       // [192][6]
    float* bi0  = (float*)(smb + OFF_BI0);
    float* bh0  = (float*)(smb + OFF_BH0);
    float* bs1  = (float*)(smb + OFF_BS1);       // bi1+bh1 (r,z)
    float* bi1n = (float*)(smb + OFF_BI1N);
    float* bh1n = (float*)(smb + OFF_BH1N);
    float* xst  = (float*)(smb + OFF_XST);       // [8][96]

    int tid = threadIdx.x, lane = tid & 31, w = tid >> 5;
    for (int i = tid; i < G * 6; i += 256) Wi0[i] = Wih0[i];
    for (int i = tid; i < G; i += 256) { bi0[i] = bih0[i]; bh0[i] = bhh0[i]; }
    for (int i = tid; i < 128; i += 256) bs1[i] = bih1[i] + bhh1[i];
    for (int i = tid; i < 64; i += 256) { bi1n[i] = bih1[128 + i]; bh1n[i] = bhh1[128 + i]; }
    {
        const float* Wsrc[3] = { Whh0, Wih1, Whh1 };
        for (int e = tid; e < 3 * 3072; e += 256) {
            int m = e / 3072, r0 = e - m * 3072;
            int ln = r0 & 31, kt = (r0 >> 5) & 3, cg = r0 >> 7;
            int g2 = ln >> 2, tq2 = ln & 3;
            int n = (cg >> 3) * 64 + (cg & 7) * 8 + g2;
            int k0 = 16 * kt + 2 * tq2;
            const float* Wp = Wsrc[m] + n * 64;
            float v0 = Wp[k0], v1 = Wp[k0 + 1], v2 = Wp[k0 + 8], v3 = Wp[k0 + 9];
            u32 hA = pkbf(v0, v1), hB = pkbf(v2, v3);
            float2 fA = upbf(hA), fB = upbf(hB);
            u32 lA = pkbf(v0 - fA.x, v1 - fA.y), lB = pkbf(v2 - fB.x, v3 - fB.y);
            WH[e] = (u64t)hA | ((u64t)hB << 32);
            WL[e] = (u64t)lA | ((u64t)lB << 32);
        }
    }
    for (int i = tid; i < 4608; i += 256) { h0h[i] = 0; h0l[i] = 0; h1h[i] = 0; h1l[i] = 0; }
    __syncthreads();

    const int g = lane >> 2, tq = lane & 3;
    const int lrow0 = w * 16;
    const int growbase = blockIdx.x * 128 + lrow0;
    // ldmatrix lane addressing
    const int lr = (lane & 7) + ((lane >> 3) & 1) * 8;
    const int lk = ((lane >> 4) & 1) * 4;
    const u32 lmo = ((lrow0 + lr) * 36 + lk) * 4;
    u32 smbase = (u32)__cvta_generic_to_shared(smb);
    const u32 a0h = smbase + OFF_H0H + lmo, a0l = smbase + OFF_H0L + lmo;
    const u32 a1h = smbase + OFF_H1H + lmo, a1l = smbase + OFF_H1L + lmo;
    float* xs = xst + w * 96;

    for (int t = 0; t < 60; t++) {
        for (int i = lane; i < 96; i += 32) {
            int rr = i / 6, dd = i - rr * 6;
            xs[i] = x[((size_t)(growbase + rr) * 60 + t) * 6 + dd];
        }
        __syncwarp();
        float xa[6], xb[6];
#pragma unroll
        for (int k = 0; k < 6; k++) { xa[k] = xs[g * 6 + k]; xb[k] = xs[(g + 8) * 6 + k]; }

        u32 A0h[4][4], A0l[4][4];
#pragma unroll
        for (int kt = 0; kt < 4; kt++) { ldm4(A0h[kt], a0h + kt * 32); ldm4(A0l[kt], a0l + kt * 32); }

        // ---------------- layer 0 ----------------
#pragma unroll 1
        for (int c = 0; c < 8; c++) {
            const int j0 = 8 * c + 2 * tq;
            float cr[4] = { dot6(xa, Wi0, j0, bi0[j0]), dot6(xa, Wi0, j0 + 1, bi0[j0 + 1]),
                            dot6(xb, Wi0, j0, bi0[j0]), dot6(xb, Wi0, j0 + 1, bi0[j0 + 1]) };
            float cz[4] = { dot6(xa, Wi0, 64 + j0, bi0[64 + j0]), dot6(xa, Wi0, 65 + j0, bi0[65 + j0]),
                            dot6(xb, Wi0, 64 + j0, bi0[64 + j0]), dot6(xb, Wi0, 65 + j0, bi0[65 + j0]) };
            float xn[4] = { dot6(xa, Wi0, 128 + j0, bi0[128 + j0]), dot6(xa, Wi0, 129 + j0, bi0[129 + j0]),
                            dot6(xb, Wi0, 128 + j0, bi0[128 + j0]), dot6(xb, Wi0, 129 + j0, bi0[129 + j0]) };
            float cn[4] = { 0.f, 0.f, 0.f, 0.f };
#pragma unroll
            for (int kt = 0; kt < 4; kt++) {
                MMA3(cr, A0h[kt], A0l[kt], WH[IX(0, 0, c, kt)], WL[IX(0, 0, c, kt)]);
                MMA3(cz, A0h[kt], A0l[kt], WH[IX(0, 1, c, kt)], WL[IX(0, 1, c, kt)]);
                MMA3(cn, A0h[kt], A0l[kt], WH[IX(0, 2, c, kt)], WL[IX(0, 2, c, kt)]);
            }
            float bR0 = bh0[j0], bR1 = bh0[j0 + 1];
            float bZ0 = bh0[64 + j0], bZ1 = bh0[65 + j0];
            float bN0 = bh0[128 + j0], bN1 = bh0[129 + j0];
            float r_0 = sigm(cr[0] + bR0), r_1 = sigm(cr[1] + bR1);
            float r_2 = sigm(cr[2] + bR0), r_3 = sigm(cr[3] + bR1);
            float z_0 = sigm(cz[0] + bZ0), z_1 = sigm(cz[1] + bZ1);
            float z_2 = sigm(cz[2] + bZ0), z_3 = sigm(cz[3] + bZ1);
            float n_0 = tanh_(xn[0] + r_0 * (cn[0] + bN0));
            float n_1 = tanh_(xn[1] + r_1 * (cn[1] + bN1));
            float n_2 = tanh_(xn[2] + r_2 * (cn[2] + bN0));
            float n_3 = tanh_(xn[3] + r_3 * (cn[3] + bN1));
            u32 ia = (lrow0 + g) * 36 + 4 * c + tq, ib = ia + 288;
            float2 hA = upbf(h0h[ia]), lA = upbf(h0l[ia]);
            float2 hB = upbf(h0h[ib]), lB = upbf(h0l[ib]);
            float v0 = (1.f - z_0) * n_0 + z_0 * (hA.x + lA.x);
            float v1 = (1.f - z_1) * n_1 + z_1 * (hA.y + lA.y);
            float v2 = (1.f - z_2) * n_2 + z_2 * (hB.x + lB.x);
            float v3 = (1.f - z_3) * n_3 + z_3 * (hB.y + lB.y);
            u32 uA = pkbf(v0, v1); float2 fA = upbf(uA);
            u32 uB = pkbf(v2, v3); float2 fB = upbf(uB);
            h0h[ia] = uA; h0l[ia] = pkbf(v0 - fA.x, v1 - fA.y);
            h0h[ib] = uB; h0l[ib] = pkbf(v2 - fB.x, v3 - fB.y);
        }
        __syncwarp();

        // ---------------- layer 1 ----------------
        u32 B0h[4][4], B0l[4][4], A1[4][4], A1b[4][4];
#pragma unroll
        for (int kt = 0; kt < 4; kt++) {
            ldm4(B0h[kt], a0h + kt * 32); ldm4(B0l[kt], a0l + kt * 32);
            ldm4(A1[kt],  a1h + kt * 32); ldm4(A1b[kt], a1l + kt * 32);
        }
#pragma unroll 1
        for (int c = 0; c < 8; c++) {
            const int j0 = 8 * c + 2 * tq;
            float cr[4] = { bs1[j0], bs1[j0 + 1], bs1[j0], bs1[j0 + 1] };
            float cz[4] = { bs1[64 + j0], bs1[65 + j0], bs1[64 + j0], bs1[65 + j0] };
            float xn[4] = { bi1n[j0], bi1n[j0 + 1], bi1n[j0], bi1n[j0 + 1] };
            float hn[4] = { bh1n[j0], bh1n[j0 + 1], bh1n[j0], bh1n[j0 + 1] };
#pragma unroll
            for (int kt = 0; kt < 4; kt++) {
                MMA3(cr, B0h[kt], B0l[kt], WH[IX(1, 0, c, kt)], WL[IX(1, 0, c, kt)]);
                MMA3(cz, B0h[kt], B0l[kt], WH[IX(1, 1, c, kt)], WL[IX(1, 1, c, kt)]);
                MMA3(xn, B0h[kt], B0l[kt], WH[IX(1, 2, c, kt)], WL[IX(1, 2, c, kt)]);
                MMA3(cr, A1[kt], A1b[kt], WH[IX(2, 0, c, kt)], WL[IX(2, 0, c, kt)]);
                MMA3(cz, A1[kt], A1b[kt], WH[IX(2, 1, c, kt)], WL[IX(2, 1, c, kt)]);
                MMA3(hn, A1[kt], A1b[kt], WH[IX(2, 2, c, kt)], WL[IX(2, 2, c, kt)]);
            }
            float r_0 = sigm(cr[0]), r_1 = sigm(cr[1]), r_2 = sigm(cr[2]), r_3 = sigm(cr[3]);
            float z_0 = sigm(cz[0]), z_1 = sigm(cz[1]), z_2 = sigm(cz[2]), z_3 = sigm(cz[3]);
            float n_0 = tanh_(xn[0] + r_0 * hn[0]);
            float n_1 = tanh_(xn[1] + r_1 * hn[1]);
            float n_2 = tanh_(xn[2] + r_2 * hn[2]);
            float n_3 = tanh_(xn[3] + r_3 * hn[3]);
            u32 ia = (lrow0 + g) * 36 + 4 * c + tq, ib = ia + 288;
            float2 hA = upbf(h1h[ia]), lA = upbf(h1l[ia]);
            float2 hB = upbf(h1h[ib]), lB = upbf(h1l[ib]);
            float v0 = (1.f - z_0) * n_0 + z_0 * (hA.x + lA.x);
            float v1 = (1.f - z_1) * n_1 + z_1 * (hA.y + lA.y);
            float v2 = (1.f - z_2) * n_2 + z_2 * (hB.x + lB.x);
            float v3 = (1.f - z_3) * n_3 + z_3 * (hB.y + lB.y);
            u32 uA = pkbf(v0, v1); float2 fA = upbf(uA);
            u32 uB = pkbf(v2, v3); float2 fB = upbf(uB);
            h1h[ia] = uA; h1l[ia] = pkbf(v0 - fA.x, v1 - fA.y);
            h1h[ib] = uB; h1l[ib] = pkbf(v2 - fB.x, v3 - fB.y);
            if (t == 59) {
                *(float2*)(hfin + (size_t)(growbase + g) * H + j0) = make_float2(v0, v1);
                *(float2*)(hfin + (size_t)(growbase + g + 8) * H + j0) = make_float2(v2, v3);
            }
        }
        __syncwarp();
    }
}

// ===== f32x2 GRU (kept for ALSTM) =====
__device__ __forceinline__ u64t pk2(float x, float y) {
    u64t r; asm("mov.b64 %0, {%1,%2};" : "=l"(r) : "f"(x), "f"(y)); return r;
}
__device__ __forceinline__ u64t ffma2(u64t a, u64t b, u64t c) {
    u64t d; asm("fma.rn.f32x2 %0, %1, %2, %3;" : "=l"(d) : "l"(a), "l"(b), "l"(c));
    return d;
}
__device__ __forceinline__ void unpk2(u64t v, float& x, float& y) {
    asm("mov.b64 {%0,%1}, %2;" : "=f"(x), "=f"(y) : "l"(v));
}
template <int DK, int RPT>
__device__ __forceinline__ void gemm_acc(
    const float* __restrict__ src, const float* __restrict__ Wt,
    u64t* A, u64t* B, u64t* C, int tx)
{
#pragma unroll 2
    for (int k = 0; k < DK; k += 2) {
        const u64t* w0r = (const u64t*)(Wt + k * G);
        const u64t* w1r = (const u64t*)(Wt + (k + 1) * G);
        u64t wa0 = w0r[tx], wb0 = w0r[tx + 32], wc0 = w0r[tx + 64];
        u64t wa1 = w1r[tx], wb1 = w1r[tx + 32], wc1 = w1r[tx + 64];
#pragma unroll
        for (int rr = 0; rr < RPT; rr++) {
            float2 hv = *(const float2*)(src + rr * DK + k);
            u64t d0 = pk2(hv.x, hv.x), d1 = pk2(hv.y, hv.y);
            A[rr] = ffma2(d0, wa0, A[rr]); B[rr] = ffma2(d0, wb0, B[rr]);
            C[rr] = ffma2(d0, wc0, C[rr]);
            A[rr] = ffma2(d1, wa1, A[rr]); B[rr] = ffma2(d1, wb1, B[rr]);
            C[rr] = ffma2(d1, wc1, C[rr]);
        }
    }
}
template <int RPT>
__device__ __forceinline__ void gru_point(
    const u64t* A, const u64t* B, const u64t* C, const u64t* XN,
    float* hw, int tx, float2* nv)
{
    const int j0 = 2 * tx;
#pragma unroll
    for (int rr = 0; rr < RPT; rr++) {
        float ra, rb, za, zb, ha, hb, xa, xb;
        unpk2(A[rr], ra, rb); unpk2(B[rr], za, zb);
        unpk2(C[rr], ha, hb); unpk2(XN[rr], xa, xb);
        float r0 = sigm(ra), r1 = sigm(rb), z0 = sigm(za), z1 = sigm(zb);
        float n0 = tanh_(xa + r0 * ha), n1 = tanh_(xb + r1 * hb);
        float2 hold = *(const float2*)(hw + rr * H + j0);
        nv[rr].x = (1.f - z0) * n0 + z0 * hold.x;
        nv[rr].y = (1.f - z1) * n1 + z1 * hold.y;
    }
    __syncwarp();
#pragma unroll
    for (int rr = 0; rr < RPT; rr++) *(float2*)(hw + rr * H + j0) = nv[rr];
    __syncwarp();
}
template <int DIN, int RPT, int WARPS, bool STORE_ALL>
__global__ __launch_bounds__(32 * WARPS, 1) void gru2_kernel(
    const float* __restrict__ x, int Tn, int Nn,
    const float* __restrict__ Wih0, const float* __restrict__ Whh0,
    const float* __restrict__ bih0, const float* __restrict__ bhh0,
    const float* __restrict__ Wih1, const float* __restrict__ Whh1,
    const float* __restrict__ bih1, const float* __restrict__ bhh1,
    float* __restrict__ out)
{
    constexpr int RP = RPT * WARPS;
    constexpr int NT = 32 * WARPS;
    constexpr int XSPAD = (RPT * DIN + 1) & ~1;
    extern __shared__ float sm[];
    float* Wti0 = sm;
    float* Wth0 = Wti0 + DIN * G;
    float* Wti1 = Wth0 + H * G;
    float* Wth1 = Wti1 + H * G;
    float* bi0 = Wth1 + H * G;
    float* bh0 = bi0 + G; float* bi1 = bh0 + G; float* bh1 = bi1 + G;
    float* h0s = bh1 + G;
    float* h1s = h0s + RP * H;
    float* xsS = h1s + RP * H;

    int tx = threadIdx.x, ty = threadIdx.y, tid = ty * 32 + tx;
    for (int idx = tid; idx < DIN * G; idx += NT) {
        int j = idx / DIN, k = idx - j * DIN;
        Wti0[k * G + j] = Wih0[idx];
    }
    for (int idx = tid; idx < H * G; idx += NT) {
        int j = idx >> 6, k = idx & 63;
        Wth0[k * G + j] = Whh0[idx]; Wti1[k * G + j] = Wih1[idx]; Wth1[k * G + j] = Whh1[idx];
    }
    for (int idx = tid; idx < G; idx += NT) {
        bi0[idx] = bih0[idx]; bh0[idx] = bhh0[idx];
        bi1[idx] = bih1[idx]; bh1[idx] = bhh1[idx];
    }
    for (int idx = tid; idx < RP * H; idx += NT) { h0s[idx] = 0.f; h1s[idx] = 0.f; }
    __syncthreads();

    const int rowbase = blockIdx.x * RP + ty * RPT;
    float* h0w = h0s + ty * RPT * H;
    float* h1w = h1s + ty * RPT * H;
    float* xw = xsS + ty * XSPAD;
    const int j0 = 2 * tx;

    for (int t = 0; t < Tn; t++) {
        for (int i = tx; i < RPT * DIN; i += 32) {
            int rr = i / DIN, dd = i - rr * DIN;
            int grow = rowbase + rr;
            xw[i] = (grow < Nn) ? x[((size_t)grow * Tn + t) * DIN + dd] : 0.f;
        }
        __syncwarp();
        u64t A[RPT], B[RPT], C[RPT], XN[RPT];
        float2 nv[RPT];
        {
            u64t bA = pk2(bi0[j0] + bh0[j0], bi0[j0 + 1] + bh0[j0 + 1]);
            u64t bB = pk2(bi0[j0 + 64] + bh0[j0 + 64], bi0[j0 + 65] + bh0[j0 + 65]);
            u64t bC = pk2(bh0[j0 + 128], bh0[j0 + 129]);
            u64t bN = pk2(bi0[j0 + 128], bi0[j0 + 129]);
#pragma unroll
            for (int rr = 0; rr < RPT; rr++) { A[rr] = bA; B[rr] = bB; C[rr] = bC; XN[rr] = bN; }
        }
        gemm_acc<DIN, RPT>(xw, Wti0, A, B, XN, tx);
        gemm_acc<H, RPT>(h0w, Wth0, A, B, C, tx);
        gru_point<RPT>(A, B, C, XN, h0w, tx, nv);
        {
            u64t bA = pk2(bi1[j0] + bh1[j0], bi1[j0 + 1] + bh1[j0 + 1]);
            u64t bB = pk2(bi1[j0 + 64] + bh1[j0 + 64], bi1[j0 + 65] + bh1[j0 + 65]);
            u64t bC = pk2(bh1[j0 + 128], bh1[j0 + 129]);
            u64t bN = pk2(bi1[j0 + 128], bi1[j0 + 129]);
#pragma unroll
            for (int rr = 0; rr < RPT; rr++) { A[rr] = bA; B[rr] = bB; C[rr] = bC; XN[rr] = bN; }
        }
        gemm_acc<H, RPT>(h0w, Wti1, A, B, XN, tx);
        gemm_acc<H, RPT>(h1w, Wth1, A, B, C, tx);
        gru_point<RPT>(A, B, C, XN, h1w, tx, nv);
        if (STORE_ALL) {
#pragma unroll
            for (int rr = 0; rr < RPT; rr++) {
                int grow = rowbase + rr;
                if (grow < Nn)
                    *(float2*)(out + ((size_t)grow * Tn + t) * H + j0) = nv[rr];
            }
        }
    }
    if (!STORE_ALL) {
#pragma unroll
        for (int rr = 0; rr < RPT; rr++) {
            int grow = rowbase + rr;
            if (grow < Nn)
                *(float2*)(out + (size_t)grow * H + j0) = *(const float2*)(h1w + rr * H + j0);
        }
    }
}

// ========== trans projection + attention score scalars ====
__global__ __launch_bounds__(64) void trans_score_kernel(
    const float* __restrict__ hfin,
    const float* __restrict__ W, const float* __restrict__ b,
    const float* __restrict__ a,
    float* __restrict__ ssrc, float* __restrict__ sdst)
{
    __shared__ float Wt[H * H], bs[H], as[2 * H], hrow[H], red[H], red2[H];
    int d = threadIdx.x;
    for (int idx = d; idx < H * H; idx += 64)
        Wt[(idx & 63) * H + (idx >> 6)] = W[idx];
    bs[d] = b[d]; as[d] = a[d]; as[H + d] = a[H + d];
    __syncthreads();
    for (int rr = 0; rr < 16; rr++) {
        int n = blockIdx.x * 16 + rr;
        hrow[d] = hfin[(size_t)n * H + d];
        __syncthreads();
        float xp = bs[d];
#pragma unroll 8
        for (int k = 0; k < H; k++) xp += hrow[k] * Wt[k * H + d];
        red[d] = xp * as[d]; red2[d] = xp * as[H + d];
        __syncthreads();
        for (int s2 = 32; s2 > 0; s2 >>= 1) {
            if (d < s2) { red[d] += red[d + s2]; red2[d] += red2[d + s2]; }
            __syncthreads();
        }
        if (d == 0) { sdst[n] = red[0]; ssrc[n] = red2[0]; }
        __syncthreads();
    }
}

// ====== GAT ======
__global__ __launch_bounds__(256, 1) void gat_kernel(
    const float* __restrict__ hfin, const float* __restrict__ ssrc,
    const float* __restrict__ sdst, const float* __restrict__ fcW,
    const float* __restrict__ fcb, float* __restrict__ h2)
{
    extern __shared__ float s[];
    float* hs = s;
    float* fWt = hs + MM * H;
    float* sd = fWt + H * H;
    float* wj = sd + MM;
    float* rowv = wj + MM;
    float* part = rowv + H;
    float* red = part + 4 * H;

    int t = threadIdx.x;
    int k = blockIdx.y;
    int base = k * MM;
    const float4* src4 = (const float4*)(hfin + (size_t)base * H);
    float4* hs4 = (float4*)hs;
    for (int idx = t; idx < MM * (H / 4); idx += 256) hs4[idx] = src4[idx];
    for (int idx = t; idx < H * H; idx += 256)
        fWt[(idx & 63) * H + (idx >> 6)] = fcW[idx];
    for (int idx = t; idx < MM; idx += 256) sd[idx] = sdst[base + idx];
    __syncthreads();

    int lane = t & 31, wid = t >> 5;
    for (int r = 0; r < 64; r++) {
        int i = blockIdx.x * 64 + r;
        float si = ssrc[base + i];
        float v0 = si + sd[t];       v0 = v0 > 0.f ? v0 : 0.01f * v0;
        float v1 = si + sd[t + 256]; v1 = v1 > 0.f ? v1 : 0.01f * v1;
        float mx = fmaxf(v0, v1);
#pragma unroll
        for (int o = 16; o > 0; o >>= 1) mx = fmaxf(mx, __shfl_xor_sync(~0u, mx, o));
        if (lane == 0) red[wid] = mx;
        __syncthreads();
        mx = red[0];
#pragma unroll
        for (int q = 1; q < 8; q++) mx = fmaxf(mx, red[q]);
        float e0 = __expf(v0 - mx), e1 = __expf(v1 - mx);
        wj[t] = e0; wj[t + 256] = e1;
        float sum = e0 + e1;
#pragma unroll
        for (int o = 16; o > 0; o >>= 1) sum += __shfl_xor_sync(~0u, sum, o);
        __syncthreads();
        if (lane == 0) red[wid] = sum;
        __syncthreads();
        sum = 0.f;
#pragma unroll
        for (int q = 0; q < 8; q++) sum += red[q];
        float inv = __fdividef(1.f, sum);
        int d = t & 63, q = t >> 6;
        float acc = 0.f;
        const float* hp = hs + q * 128 * H + d;
        const float* wp = wj + q * 128;
#pragma unroll 8
        for (int j = 0; j < 128; j++) acc += wp[j] * hp[j * H];
        part[q * H + d] = acc;
        __syncthreads();
        if (t < H)
            rowv[t] = (part[t] + part[H + t] + part[2 * H + t] + part[3 * H + t]) * inv
                      + hs[i * H + t];
        __syncthreads();
        if (t < H) {
            float acc2 = fcb[t];
#pragma unroll 8
            for (int dd = 0; dd < H; dd++) acc2 += rowv[dd] * fWt[dd * H + t];
            h2[((size_t)i * NK + k) * H + t] = acc2;
        }
        __syncthreads();
    }
}

// ============== al_in tanh ==============
__global__ __launch_bounds__(64) void lin_tanh_kernel(
    const float* __restrict__ in, const float* __restrict__ W,
    const float* __restrict__ b, float* __restrict__ out)
{
    __shared__ float Wt[H * H], bs[H], hrow[H];
    int d = threadIdx.x;
    for (int idx = d; idx < H * H; idx += 64)
        Wt[(idx & 63) * H + (idx >> 6)] = W[idx];
    bs[d] = b[d];
    __syncthreads();
    for (int rr = 0; rr < 16; rr++) {
        size_t n = (size_t)blockIdx.x * 16 + rr;
        hrow[d] = in[n * H + d];
        __syncthreads();
        float acc = bs[d];
#pragma unroll 8
        for (int k = 0; k < H; k++) acc += hrow[k] * Wt[k * H + d];
        out[n * H + d] = tanhf(acc);
        __syncthreads();
    }
}

// ============== ALSTM attention + outputs ==============
__global__ __launch_bounds__(64) void final_kernel(
    const float* __restrict__ r, const float* __restrict__ h2,
    const float* __restrict__ att1W, const float* __restrict__ att1b,
    const float* __restrict__ att2W,
    const float* __restrict__ aloutW, const float* __restrict__ aloutb,
    const float* __restrict__ fcoW, const float* __restrict__ fcob,
    float* __restrict__ out)
{
    __shared__ float a1t[32 * H];
    __shared__ float e[NK], rrow[H], red2[2];
    int t = threadIdx.x;
    int n = blockIdx.x;
    for (int idx = t; idx < 32 * H; idx += 64)
        a1t[(idx & 63) * 32 + (idx >> 6)] = att1W[idx];
    __syncthreads();
    for (int tt = 0; tt < NK; tt++) {
        rrow[t] = r[((size_t)n * NK + tt) * H + t];
        __syncthreads();
        if (t < 32) {
            float acc = att1b[t];
#pragma unroll 8
            for (int k = 0; k < H; k++) acc += rrow[k] * a1t[k * 32 + t];
            float v = tanhf(acc) * att2W[t];
#pragma unroll
            for (int o = 16; o > 0; o >>= 1) v += __shfl_xor_sync(~0u, v, o);
            if (t == 0) e[tt] = v;
        }
        __syncthreads();
    }
    float mx = e[0];
#pragma unroll
    for (int tt = 1; tt < NK; tt++) mx = fmaxf(mx, e[tt]);
    float sum = 0.f;
#pragma unroll
    for (int tt = 0; tt < NK; tt++) sum += __expf(e[tt] - mx);
    float inv = __fdividef(1.f, sum);
    float oa = 0.f;
#pragma unroll
    for (int tt = 0; tt < NK; tt++)
        oa += __expf(e[tt] - mx) * inv * r[((size_t)n * NK + tt) * H + t];
    float rl = r[((size_t)n * NK + (NK - 1)) * H + t];
    float p = rl * aloutW[t] + oa * aloutW[H + t];
#pragma unroll
    for (int o = 16; o > 0; o >>= 1) p += __shfl_xor_sync(~0u, p, o);
    if ((t & 31) == 0) red2[t >> 5] = p;
    __syncthreads();
    if (t == 0) out[n] = red2[0] + red2[1] + aloutb[0];
    __syncthreads();
    float hv = h2[((size_t)n * NK + (NK - 1)) * H + t];
    hv = hv > 0.f ? hv : 0.01f * hv;
    float pp = hv * fcoW[t];
#pragma unroll
    for (int o = 16; o > 0; o >>= 1) pp += __shfl_xor_sync(~0u, pp, o);
    if ((t & 31) == 0) red2[t >> 5] = pp;
    __syncthreads();
    if (t == 0) out[MM + n] = red2[0] + red2[1] + fcob[0];
}

// ============================ launcher ============================
extern "C" void kernel_launch(void* const* d_in, const int* in_sizes, int n_in,
                              void* d_out, int out_size) {
    const float* x       = (const float*)d_in[0];
    const float* rWih0   = (const float*)d_in[1];
    const float* rWhh0   = (const float*)d_in[2];
    const float* rbih0   = (const float*)d_in[3];
    const float* rbhh0   = (const float*)d_in[4];
    const float* rWih1   = (const float*)d_in[5];
    const float* rWhh1   = (const float*)d_in[6];
    const float* rbih1   = (const float*)d_in[7];
    const float* rbhh1   = (const float*)d_in[8];
    const float* trans_W = (const float*)d_in[9];
    const float* trans_b = (const float*)d_in[10];
    const float* a_vec   = (const float*)d_in[11];
    const float* fc_W    = (const float*)d_in[12];
    const float* fc_b    = (const float*)d_in[13];
    const float* fco_W   = (const float*)d_in[14];
    const float* fco_b   = (const float*)d_in[15];
    const float* al_in_W = (const float*)d_in[16];
    const float* al_in_b = (const float*)d_in[17];
    const float* aWih0   = (const float*)d_in[18];
    const float* aWhh0   = (const float*)d_in[19];
    const float* abih0   = (const float*)d_in[20];
    const float* abhh0   = (const float*)d_in[21];
    const float* aWih1   = (const float*)d_in[22];
    const float* aWhh1   = (const float*)d_in[23];
    const float* abih1   = (const float*)d_in[24];
    const float* abhh1   = (const float*)d_in[25];
    const float* att1_W  = (const float*)d_in[26];
    const float* att1_b  = (const float*)d_in[27];
    const float* att2_W  = (const float*)d_in[28];
    const float* alout_W = (const float*)d_in[29];
    const float* alout_b = (const float*)d_in[30];

    float *hfin, *ssrc, *sdst, *h2, *z, *r;
    cudaGetSymbolAddress((void**)&hfin, g_hfin);
    cudaGetSymbolAddress((void**)&ssrc, g_ssrc);
    cudaGetSymbolAddress((void**)&sdst, g_sdst);
    cudaGetSymbolAddress((void**)&h2, g_h2);
    cudaGetSymbolAddress((void**)&z, g_z);
    cudaGetSymbolAddress((void**)&r, g_r);

    const size_t smem3 = (size_t)(4 * H * G + 4 * G + 2 * 4 * H + 4 * 64) * 4;
    const size_t smemg = (size_t)(MM * H + H * H + MM + MM + H + 4 * H + 8) * 4;

    cudaFuncSetAttribute(gru_tc_kernel,
                         cudaFuncAttributeMaxDynamicSharedMemorySize, SMEM_TC);
    cudaFuncSetAttribute(gru2_kernel<64, 1, 4, true>,
                         cudaFuncAttributeMaxDynamicSharedMemorySize, (int)smem3);
    cudaFuncSetAttribute(gat_kernel,
                         cudaFuncAttributeMaxDynamicSharedMemorySize, (int)smemg);

    gru_tc_kernel<<<80, 256, SMEM_TC>>>(
        x, rWih0, rbih0, rWhh0, rbhh0, rWih1, rbih1, rWhh1, rbhh1, hfin);
    trans_score_kernel<<<640, 64>>>(hfin, trans_W, trans_b, a_vec, ssrc, sdst);
    gat_kernel<<<dim3(8, NK), 256, smemg>>>(hfin, ssrc, sdst, fc_W, fc_b, h2);
    lin_tanh_kernel<<<640, 64>>>(h2, al_in_W, al_in_b, z);
    gru2_kernel<64, 1, 4, true><<<128, dim3(32, 4), smem3>>>(
        z, NK, MM, aWih0, aWhh0, abih0, abhh0, aWih1, aWhh1, abih1, abhh1, r);
    final_kernel<<<MM, 64>>>(r, h2, att1_W, att1_b, att2_W,
                             alout_W, alout_b, fco_W, fco_b, (float*)d_out);
}